// round 8
// baseline (speedup 1.0000x reference)
#include <cuda_runtime.h>
#include <cuda_fp16.h>
#include <cstdint>

// Problem constants
constexpr int Bsz = 4;
constexpr int Sq  = 2048;
constexpr int Dm  = 1024;

// Scratch (device globals; no allocation allowed).
// "blocked" fp16 layout: matrix [R x K] split into 16x16 blocks, block
// (br,bk) stored at (br*(K/16)+bk)*256 halves; inside a block, 16B chunk
// (g,q), g=0..7,q=0..3 (chunk idx = g*4+q), holds halves
//   x: [row g,   k 2q,2q+1]   y: [row g,   k 2q+8,2q+9]
//   z: [row g+8, k 2q,2q+1]   w: [row g+8, k 2q+8,2q+9]
// One LDS.128 = one full m16n8k16 A-fragment (regs x,z,y,w) or two
// B-fragments (n=g via x,y and n=g+8 via z,w).
__device__ __half g_Xh [(long)Bsz * Sq * Dm];
__device__ __half g_WqT[(long)Dm * Dm];
__device__ __half g_WkT[(long)Dm * Dm];
__device__ __half g_WvT[(long)Dm * Dm];
__device__ __half g_Qh [(long)Bsz * Sq * Dm];
__device__ __half g_Kh [(long)Bsz * Sq * Dm];
__device__ float  g_V  [(long)Bsz * Sq * Dm];   // fp32 row-major (pre-transpose)
__device__ __half g_Vt [(long)Bsz * Sq * Dm];   // V^T per batch, blocked
__device__ float  g_S  [(long)Bsz * Sq * Sq];   // fp32 scores, row-major
__device__ __half g_Ph [(long)Bsz * Sq * Sq];   // fp16 probs, blocked

// ---------------------------------------------------------------------------
// helpers
// ---------------------------------------------------------------------------
__device__ __forceinline__ void cp16(void* s, const void* g) {
    uint32_t sa = (uint32_t)__cvta_generic_to_shared(s);
    asm volatile("cp.async.cg.shared.global [%0], [%1], 16;\n" :: "r"(sa), "l"(g));
}

__device__ __forceinline__ void mma_f16(float* d,
    uint32_t a0, uint32_t a1, uint32_t a2, uint32_t a3,
    uint32_t b0, uint32_t b1) {
    asm volatile(
        "mma.sync.aligned.m16n8k16.row.col.f32.f16.f16.f32 "
        "{%0,%1,%2,%3},{%4,%5,%6,%7},{%8,%9},{%0,%1,%2,%3};"
        : "+f"(d[0]), "+f"(d[1]), "+f"(d[2]), "+f"(d[3])
        : "r"(a0), "r"(a1), "r"(a2), "r"(a3), "r"(b0), "r"(b1));
}

__device__ __forceinline__ uint32_t pack2(float a, float b) {
    __half2 h = __floats2half2_rn(a, b);
    return *(uint32_t*)&h;
}

__device__ __forceinline__ float warp_max(float v) {
    #pragma unroll
    for (int o = 16; o; o >>= 1) v = fmaxf(v, __shfl_xor_sync(0xFFFFFFFFu, v, o));
    return v;
}
__device__ __forceinline__ float warp_sum(float v) {
    #pragma unroll
    for (int o = 16; o; o >>= 1) v += __shfl_xor_sync(0xFFFFFFFFu, v, o);
    return v;
}

// half offset of (r, k) pair start (k even) inside blocked [R x K] matrix
__device__ __forceinline__ long blk_off(int r, int k, int Kd) {
    return ((long)(r >> 4) * (Kd >> 4) + (k >> 4)) * 256
         + ((r & 7) * 4 + ((k >> 1) & 3)) * 8
         + ((r >> 3) & 1) * 4 + ((k >> 3) & 1) * 2;
}

// ---------------------------------------------------------------------------
// Pack fp32 row-major [R x Kd] -> fp16 blocked.  One 16B chunk (8 halves)
// per thread; nchunks = R*Kd/8.
// ---------------------------------------------------------------------------
__global__ void __launch_bounds__(256)
pack_rm(const float* __restrict__ in, __half* __restrict__ out,
        int Kd, long nchunks)
{
    long c = (long)blockIdx.x * blockDim.x + threadIdx.x;
    if (c >= nchunks) return;
    const long blk = c >> 5;
    const int idx = (int)(c & 31);
    const int g = idx >> 2, q = idx & 3;
    const int Kb = Kd >> 4;
    const int rb = (int)(blk / Kb), kb = (int)(blk % Kb);
    const int r = rb * 16 + g, k0 = kb * 16 + q * 2;
    const float* p = in + (long)r * Kd + k0;
    float2 a   = *(const float2*)p;
    float2 b   = *(const float2*)(p + 8);
    float2 clo = *(const float2*)(p + (long)8 * Kd);
    float2 chi = *(const float2*)(p + (long)8 * Kd + 8);
    uint4 u;
    u.x = pack2(a.x, a.y);     u.y = pack2(b.x, b.y);
    u.z = pack2(clo.x, clo.y); u.w = pack2(chi.x, chi.y);
    ((uint4*)out)[c] = u;
}

// ---------------------------------------------------------------------------
// Transpose fp32 [Rin x Cin] (per batch z) -> fp16 blocked [Cin x Rin].
// 32x32 tiles; 128 of the 256 threads each emit one 16B chunk.
// ---------------------------------------------------------------------------
__global__ void __launch_bounds__(256)
pack_t(const float* __restrict__ in, __half* __restrict__ out, int Rin, int Cin)
{
    __shared__ float t[32][33];
    in  += (long)blockIdx.z * Rin * Cin;
    out += (long)blockIdx.z * Rin * Cin;
    const int r0 = blockIdx.x * 32, c0 = blockIdx.y * 32;
    const int x = threadIdx.x, y = threadIdx.y;     // (32, 8)
    #pragma unroll
    for (int i = 0; i < 32; i += 8)
        t[y + i][x] = in[(long)(r0 + y + i) * Cin + c0 + x];
    __syncthreads();

    const int tid = y * 32 + x;
    if (tid < 128) {
        const int blk = tid >> 5, idx = tid & 31;
        const int brl = blk >> 1, bkl = blk & 1;
        const int g = idx >> 2, q = idx & 3;
        const int E  = 16 * brl + g;       // out-row within 32 (orig col)
        const int S0 = 16 * bkl + 2 * q;   // out-k within 32 (orig row)
        uint4 u;
        u.x = pack2(t[S0][E],         t[S0 + 1][E]);
        u.y = pack2(t[S0 + 8][E],     t[S0 + 9][E]);
        u.z = pack2(t[S0][E + 8],     t[S0 + 1][E + 8]);
        u.w = pack2(t[S0 + 8][E + 8], t[S0 + 9][E + 8]);
        const long chunk =
            ((long)((c0 >> 4) + brl) * (Rin >> 4) + (r0 >> 4) + bkl) * 32 + idx;
        ((uint4*)out)[chunk] = u;
    }
}

// ---------------------------------------------------------------------------
// FP16 mma.sync GEMM on blocked operands:  C[M,N] = A[M,K] * B[N,K]^T
// CTA 64(M) x 256(N), 8 warps (2x4), warp tile 32x64, K-chunk 16,
// 4-stage cp.async pipeline, ONE __syncthreads per K-chunk.
// Per warp-chunk: 6 LDS.128 + 16 HMMA.16816.
// EPI_F16: write C into fp16 blocked layout; else fp32 row-major.
// ---------------------------------------------------------------------------
template <bool CAUSAL_SKIP, bool KLIMIT, bool EPI_F16>
__global__ void __launch_bounds__(256)
hgemm(const __half* __restrict__ A, const __half* __restrict__ B, void* Cout,
      int Kd, int ldc, long sA, long sB, long sC)
{
    const int m0 = blockIdx.y * 64;
    const int n0 = blockIdx.x * 256;
    if (CAUSAL_SKIP && n0 > m0 + 63) return;

    A += (long)blockIdx.z * sA;
    B += (long)blockIdx.z * sB;

    const int Keff = KLIMIT ? min(Kd, m0 + 64) : Kd;
    const int nkt  = Keff >> 4;
    const int Kb   = Kd >> 4;

    __shared__ uint4 sm[4][640];   // per stage: A chunks [0,128), B [128,640)

    const int tid  = threadIdx.x;
    const int warp = tid >> 5;
    const int lane = tid & 31;
    const int wm   = warp >> 2;    // 0..1  (32 M-rows each)
    const int wn   = warp & 3;     // 0..3  (64 N-cols each)

    // loaders: A = 128 chunks (threads 0..127, 1 each); B = 512 chunks (2 each)
    const uint4* ag = (const uint4*)A
        + ((long)((m0 >> 4) + warp) * Kb) * 32 + lane;           // warps 0..3
    const uint4* bg0 = (const uint4*)B
        + ((long)((n0 >> 4) + (tid >> 5)) * Kb) * 32 + lane;
    const uint4* bg1 = bg0 + (long)8 * Kb * 32;                  // +8 block rows

    auto load_stage = [&](int st, int kt) {
        if (tid < 128) cp16(&sm[st][tid], ag + kt * 32);
        cp16(&sm[st][128 + tid],       bg0 + kt * 32);
        cp16(&sm[st][128 + tid + 256], bg1 + kt * 32);
    };

    #pragma unroll
    for (int s = 0; s < 3; s++) {
        if (s < nkt) load_stage(s, s);
        asm volatile("cp.async.commit_group;\n");
    }

    float acc[2][8][4] = {};

    for (int kt = 0; kt < nkt; ++kt) {
        const int cur = kt & 3;
        asm volatile("cp.async.wait_group 2;\n");
        __syncthreads();   // data ready + all warps done reading slot (kt+3)&3

        if (kt + 3 < nkt) load_stage((kt + 3) & 3, kt + 3);
        asm volatile("cp.async.commit_group;\n");

        uint4 Aq[2], Bq[4];
        #pragma unroll
        for (int mi = 0; mi < 2; mi++)
            Aq[mi] = sm[cur][(wm * 2 + mi) * 32 + lane];
        #pragma unroll
        for (int nj = 0; nj < 4; nj++)
            Bq[nj] = sm[cur][128 + (wn * 4 + nj) * 32 + lane];

        #pragma unroll
        for (int mi = 0; mi < 2; mi++)
            #pragma unroll
            for (int nj = 0; nj < 4; nj++) {
                mma_f16(acc[mi][nj * 2],     Aq[mi].x, Aq[mi].z, Aq[mi].y, Aq[mi].w,
                        Bq[nj].x, Bq[nj].y);
                mma_f16(acc[mi][nj * 2 + 1], Aq[mi].x, Aq[mi].z, Aq[mi].y, Aq[mi].w,
                        Bq[nj].z, Bq[nj].w);
            }
    }

    // Epilogue
    if (EPI_F16) {
        __half* Ch = (__half*)Cout;   // blocked layout, no batch (proj only)
        #pragma unroll
        for (int mi = 0; mi < 2; mi++) {
            #pragma unroll
            for (int nt = 0; nt < 8; nt++) {
                const int r0 = m0 + wm * 32 + mi * 16 + (lane >> 2);
                const int c0 = n0 + wn * 64 + nt * 8 + 2 * (lane & 3);
                const long off = blk_off(r0, c0, ldc);
                *(uint32_t*)(Ch + off)     = pack2(acc[mi][nt][0], acc[mi][nt][1]);
                *(uint32_t*)(Ch + off + 4) = pack2(acc[mi][nt][2], acc[mi][nt][3]);
            }
        }
    } else {
        float* Cf = (float*)Cout + (long)blockIdx.z * sC;
        #pragma unroll
        for (int mi = 0; mi < 2; mi++) {
            #pragma unroll
            for (int nt = 0; nt < 8; nt++) {
                const int r0 = m0 + wm * 32 + mi * 16 + (lane >> 2);
                const int c0 = n0 + wn * 64 + nt * 8 + 2 * (lane & 3);
                *(float2*)&Cf[(long)r0 * ldc + c0] =
                    make_float2(acc[mi][nt][0], acc[mi][nt][1]);
                *(float2*)&Cf[(long)(r0 + 8) * ldc + c0] =
                    make_float2(acc[mi][nt][2], acc[mi][nt][3]);
            }
        }
    }
}

// ---------------------------------------------------------------------------
// Causal row softmax: fp32 scores (row-major) -> fp16 probs (blocked).
// Logits s/32.  Zero-fills [len, ceil64(len)) so the PV GEMM (Keff=m0+64)
// reads only valid data.
// ---------------------------------------------------------------------------
__global__ void __launch_bounds__(256)
softmax_k(const float* __restrict__ S, __half* __restrict__ Ph)
{
    const int row = blockIdx.x;
    const int b = row >> 11;
    const int i = row & 2047;
    const float* p = S + ((long)b * Sq + i) * Sq;
    __half* ph = Ph + (long)b * Sq * Sq;
    const int tid = threadIdx.x;
    const int len = i + 1;
    const int lenPad = (len + 63) & ~63;
    const int npairs = lenPad >> 1;

    float e[4][2];
    #pragma unroll
    for (int k = 0; k < 4; k++) {
        const int j2 = tid + 256 * k;
        if (j2 < npairs) {
            const float2 v = *(const float2*)(p + 2 * j2);
            const int j = 2 * j2;
            e[k][0] = (j     < len) ? v.x : -3.4e38f;
            e[k][1] = (j + 1 < len) ? v.y : -3.4e38f;
        } else {
            e[k][0] = e[k][1] = -3.4e38f;
        }
    }

    float mx = -3.4e38f;
    #pragma unroll
    for (int k = 0; k < 4; k++) mx = fmaxf(mx, fmaxf(e[k][0], e[k][1]));
    mx = warp_max(mx);

    __shared__ float red[8];
    if ((tid & 31) == 0) red[tid >> 5] = mx;
    __syncthreads();
    mx = red[0];
    #pragma unroll
    for (int w = 1; w < 8; w++) mx = fmaxf(mx, red[w]);

    float s = 0.f;
    #pragma unroll
    for (int k = 0; k < 4; k++) {
        e[k][0] = __expf((e[k][0] - mx) * 0.03125f);
        e[k][1] = __expf((e[k][1] - mx) * 0.03125f);
        s += e[k][0] + e[k][1];
    }
    s = warp_sum(s);
    __syncthreads();
    if ((tid & 31) == 0) red[tid >> 5] = s;
    __syncthreads();
    float tot = 0.f;
    #pragma unroll
    for (int w = 0; w < 8; w++) tot += red[w];
    const float inv = 1.0f / tot;

    #pragma unroll
    for (int k = 0; k < 4; k++) {
        const int j2 = tid + 256 * k;
        if (j2 < npairs) {
            const int j = 2 * j2;
            *(uint32_t*)(ph + blk_off(i, j, Sq)) =
                pack2(e[k][0] * inv, e[k][1] * inv);
        }
    }
}

// ---------------------------------------------------------------------------
extern "C" void kernel_launch(void* const* d_in, const int* in_sizes, int n_in,
                              void* d_out, int out_size)
{
    const float* x  = (const float*)d_in[0];
    const float* Wq = (const float*)d_in[1];
    const float* Wk = (const float*)d_in[2];
    const float* Wv = (const float*)d_in[3];
    float* out = (float*)d_out;

    __half *Xh, *WqT, *WkT, *WvT, *Qh, *Kh, *Vt, *Ph;
    float *V, *Sb;
    cudaGetSymbolAddress((void**)&Xh,  g_Xh);
    cudaGetSymbolAddress((void**)&WqT, g_WqT);
    cudaGetSymbolAddress((void**)&WkT, g_WkT);
    cudaGetSymbolAddress((void**)&WvT, g_WvT);
    cudaGetSymbolAddress((void**)&Qh,  g_Qh);
    cudaGetSymbolAddress((void**)&Kh,  g_Kh);
    cudaGetSymbolAddress((void**)&V,   g_V);
    cudaGetSymbolAddress((void**)&Vt,  g_Vt);
    cudaGetSymbolAddress((void**)&Sb,  g_S);
    cudaGetSymbolAddress((void**)&Ph,  g_Ph);

    const int M = Bsz * Sq;   // 8192

    // 0) pack x (row-major fp32 -> blocked fp16); pack W^T (transpose+blocked)
    {
        const long nchunks = (long)M * Dm / 8;    // 16B chunks (8 halves each)
        pack_rm<<<(int)((nchunks + 255) / 256), 256>>>(x, Xh, Dm, nchunks);
        dim3 tb(32, 8);
        dim3 gw(Dm / 32, Dm / 32, 1);
        pack_t<<<gw, tb>>>(Wq, WqT, Dm, Dm);
        pack_t<<<gw, tb>>>(Wk, WkT, Dm, Dm);
        pack_t<<<gw, tb>>>(Wv, WvT, Dm, Dm);
    }

    // 1) Projections: Q,K -> fp16 blocked directly; V -> fp32 row-major
    {
        dim3 grid(Dm / 256, M / 64, 1);
        hgemm<false, false, true ><<<grid, 256>>>(Xh, WqT, Qh, Dm, Dm, 0, 0, 0);
        hgemm<false, false, true ><<<grid, 256>>>(Xh, WkT, Kh, Dm, Dm, 0, 0, 0);
        hgemm<false, false, false><<<grid, 256>>>(Xh, WvT, V,  Dm, Dm, 0, 0, 0);
    }

    // 2) Scores: S_b = Q_b K_b^T (causal-skip), fp32 row-major out
    {
        dim3 grid(Sq / 256, Sq / 64, Bsz);
        hgemm<true, false, false><<<grid, 256>>>(
            Qh, Kh, Sb, Dm, Sq,
            (long)Sq * Dm, (long)Sq * Dm, (long)Sq * Sq);
    }

    // 3) Softmax -> fp16 blocked probs
    softmax_k<<<Bsz * Sq, 256>>>(Sb, Ph);

    // 4) V^T pack, then O = P Vt^T (causal K-limit), fp32 out
    {
        dim3 tb(32, 8);
        pack_t<<<dim3(Sq / 32, Dm / 32, Bsz), tb>>>(V, Vt, Sq, Dm);
        dim3 grid(Dm / 256, Sq / 64, Bsz);
        hgemm<false, true, false><<<grid, 256>>>(
            Ph, Vt, out, Sq, Dm,
            (long)Sq * Sq, (long)Sq * Dm, (long)Sq * Dm);
    }

    (void)in_sizes; (void)n_in; (void)out_size;
}

// round 9
// speedup vs baseline: 1.1457x; 1.1457x over previous
#include <cuda_runtime.h>
#include <cuda_fp16.h>
#include <cstdint>

// Problem constants
constexpr int Bsz = 4;
constexpr int Sq  = 2048;
constexpr int Dm  = 1024;

// Scratch (device globals; no allocation allowed).
// "blocked" fp16 layout: matrix [R x K] split into 16x16 blocks, block
// (br,bk) stored at (br*(K/16)+bk)*256 halves; inside a block, 16B chunk
// (g,q), g=0..7,q=0..3 (chunk idx = g*4+q), holds halves
//   x: [row g,   k 2q,2q+1]   y: [row g,   k 2q+8,2q+9]
//   z: [row g+8, k 2q,2q+1]   w: [row g+8, k 2q+8,2q+9]
// One LDS.128 = one full m16n8k16 A-fragment (regs x,z,y,w) or two
// B-fragments (n=g via x,y and n=g+8 via z,w).
__device__ __half g_Xh [(long)Bsz * Sq * Dm];
__device__ __half g_WqT[(long)Dm * Dm];
__device__ __half g_WkT[(long)Dm * Dm];
__device__ __half g_WvT[(long)Dm * Dm];
__device__ __half g_Qh [(long)Bsz * Sq * Dm];
__device__ __half g_Kh [(long)Bsz * Sq * Dm];
__device__ float  g_V  [(long)Bsz * Sq * Dm];   // fp32 row-major (pre-transpose)
__device__ __half g_Vt [(long)Bsz * Sq * Dm];   // V^T per batch, blocked
__device__ float  g_S  [(long)Bsz * Sq * Sq];   // fp32 scores, row-major
__device__ __half g_Ph [(long)Bsz * Sq * Sq];   // fp16 probs, blocked

// ---------------------------------------------------------------------------
// helpers
// ---------------------------------------------------------------------------
__device__ __forceinline__ void cp16(void* s, const void* g) {
    uint32_t sa = (uint32_t)__cvta_generic_to_shared(s);
    asm volatile("cp.async.cg.shared.global [%0], [%1], 16;\n" :: "r"(sa), "l"(g));
}

__device__ __forceinline__ void mma_f16(float* d,
    uint32_t a0, uint32_t a1, uint32_t a2, uint32_t a3,
    uint32_t b0, uint32_t b1) {
    asm volatile(
        "mma.sync.aligned.m16n8k16.row.col.f32.f16.f16.f32 "
        "{%0,%1,%2,%3},{%4,%5,%6,%7},{%8,%9},{%0,%1,%2,%3};"
        : "+f"(d[0]), "+f"(d[1]), "+f"(d[2]), "+f"(d[3])
        : "r"(a0), "r"(a1), "r"(a2), "r"(a3), "r"(b0), "r"(b1));
}

__device__ __forceinline__ uint32_t pack2(float a, float b) {
    __half2 h = __floats2half2_rn(a, b);
    return *(uint32_t*)&h;
}

__device__ __forceinline__ float warp_max(float v) {
    #pragma unroll
    for (int o = 16; o; o >>= 1) v = fmaxf(v, __shfl_xor_sync(0xFFFFFFFFu, v, o));
    return v;
}
__device__ __forceinline__ float warp_sum(float v) {
    #pragma unroll
    for (int o = 16; o; o >>= 1) v += __shfl_xor_sync(0xFFFFFFFFu, v, o);
    return v;
}

// half offset of (r, k) pair start (k even) inside blocked [R x K] matrix
__device__ __forceinline__ long blk_off(int r, int k, int Kd) {
    return ((long)(r >> 4) * (Kd >> 4) + (k >> 4)) * 256
         + ((r & 7) * 4 + ((k >> 1) & 3)) * 8
         + ((r >> 3) & 1) * 4 + ((k >> 3) & 1) * 2;
}

// ---------------------------------------------------------------------------
// Pack fp32 row-major [R x Kd] -> fp16 blocked.  One 16B chunk (8 halves)
// per thread; nchunks = R*Kd/8.
// ---------------------------------------------------------------------------
__global__ void __launch_bounds__(256)
pack_rm(const float* __restrict__ in, __half* __restrict__ out,
        int Kd, long nchunks)
{
    long c = (long)blockIdx.x * blockDim.x + threadIdx.x;
    if (c >= nchunks) return;
    const long blk = c >> 5;
    const int idx = (int)(c & 31);
    const int g = idx >> 2, q = idx & 3;
    const int Kb = Kd >> 4;
    const int rb = (int)(blk / Kb), kb = (int)(blk % Kb);
    const int r = rb * 16 + g, k0 = kb * 16 + q * 2;
    const float* p = in + (long)r * Kd + k0;
    float2 a   = *(const float2*)p;
    float2 b   = *(const float2*)(p + 8);
    float2 clo = *(const float2*)(p + (long)8 * Kd);
    float2 chi = *(const float2*)(p + (long)8 * Kd + 8);
    uint4 u;
    u.x = pack2(a.x, a.y);     u.y = pack2(b.x, b.y);
    u.z = pack2(clo.x, clo.y); u.w = pack2(chi.x, chi.y);
    ((uint4*)out)[c] = u;
}

// ---------------------------------------------------------------------------
// Transpose fp32 [Rin x Cin] (per batch z) -> fp16 blocked [Cin x Rin].
// 32x32 tiles; 128 of the 256 threads each emit one 16B chunk.
// ---------------------------------------------------------------------------
__global__ void __launch_bounds__(256)
pack_t(const float* __restrict__ in, __half* __restrict__ out, int Rin, int Cin)
{
    __shared__ float t[32][33];
    in  += (long)blockIdx.z * Rin * Cin;
    out += (long)blockIdx.z * Rin * Cin;
    const int r0 = blockIdx.x * 32, c0 = blockIdx.y * 32;
    const int x = threadIdx.x, y = threadIdx.y;     // (32, 8)
    #pragma unroll
    for (int i = 0; i < 32; i += 8)
        t[y + i][x] = in[(long)(r0 + y + i) * Cin + c0 + x];
    __syncthreads();

    const int tid = y * 32 + x;
    if (tid < 128) {
        const int blk = tid >> 5, idx = tid & 31;
        const int brl = blk >> 1, bkl = blk & 1;
        const int g = idx >> 2, q = idx & 3;
        const int E  = 16 * brl + g;       // out-row within 32 (orig col)
        const int S0 = 16 * bkl + 2 * q;   // out-k within 32 (orig row)
        uint4 u;
        u.x = pack2(t[S0][E],         t[S0 + 1][E]);
        u.y = pack2(t[S0 + 8][E],     t[S0 + 9][E]);
        u.z = pack2(t[S0][E + 8],     t[S0 + 1][E + 8]);
        u.w = pack2(t[S0 + 8][E + 8], t[S0 + 9][E + 8]);
        const long chunk =
            ((long)((c0 >> 4) + brl) * (Rin >> 4) + (r0 >> 4) + bkl) * 32 + idx;
        ((uint4*)out)[chunk] = u;
    }
}

// ---------------------------------------------------------------------------
// FP16 mma.sync GEMM on blocked operands:  C[M,N] = A[M,K] * B[N,K]^T
// CTA 64(M) x 128(N), 8 warps (2x4), warp tile 32x32.
// K-chunk 32 per pipeline stage (two 16-K blocks), 4 stages, ONE
// __syncthreads per chunk.  Per iter per warp: 8 LDS.128 + 16 HMMA.
// EPI_F16: write C into fp16 blocked layout; else fp32 row-major.
// ---------------------------------------------------------------------------
template <bool CAUSAL_SKIP, bool KLIMIT, bool EPI_F16>
__global__ void __launch_bounds__(256)
hgemm(const __half* __restrict__ A, const __half* __restrict__ B, void* Cout,
      int Kd, int ldc, long sA, long sB, long sC)
{
    const int m0 = blockIdx.y * 64;
    const int n0 = blockIdx.x * 128;
    if (CAUSAL_SKIP && n0 > m0 + 63) return;

    A += (long)blockIdx.z * sA;
    B += (long)blockIdx.z * sB;

    const int Keff = KLIMIT ? min(Kd, m0 + 64) : Kd;
    const int nkt  = Keff >> 5;          // K-chunks of 32 (Keff always mult of 64)
    const int Kb   = Kd >> 4;            // 16-K blocks per row

    // per stage: A [0,256) = kb*128 + mb*32 + lane ; B [256,768) = 256 + kb*256 + nb*32 + lane
    __shared__ uint4 sm[4][768];         // 48 KB

    const int tid  = threadIdx.x;
    const int warp = tid >> 5;
    const int lane = tid & 31;
    const int wm   = warp >> 2;          // 0..1
    const int wn   = warp & 3;           // 0..3

    // A loader: 256 chunks, 1/thread
    const int akb = tid >> 7;            // 0..1
    const int amb = (tid >> 5) & 3;      // 0..3
    const uint4* ag = (const uint4*)A + ((long)((m0 >> 4) + amb) * Kb + akb) * 32 + lane;
    const int asmi = akb * 128 + amb * 32 + lane;
    // B loader: 512 chunks, 2/thread (kb = i, nb = warp)
    const uint4* bg0 = (const uint4*)B + ((long)((n0 >> 4) + warp) * Kb + 0) * 32 + lane;
    const uint4* bg1 = (const uint4*)B + ((long)((n0 >> 4) + warp) * Kb + 1) * 32 + lane;
    const int bsmi0 = 256 +       warp * 32 + lane;
    const int bsmi1 = 256 + 256 + warp * 32 + lane;

    auto load_stage = [&](int st, int kt) {
        const long koff = (long)kt * 64;   // 2 blocks of 32 chunks
        cp16(&sm[st][asmi],  ag  + koff);
        cp16(&sm[st][bsmi0], bg0 + koff);
        cp16(&sm[st][bsmi1], bg1 + koff);
    };

    #pragma unroll
    for (int s = 0; s < 3; s++) {
        if (s < nkt) load_stage(s, s);
        asm volatile("cp.async.commit_group;\n");
    }

    float acc[2][4][4] = {};

    for (int kt = 0; kt < nkt; ++kt) {
        const int cur = kt & 3;
        asm volatile("cp.async.wait_group 2;\n");
        __syncthreads();   // data ready + all warps done reading slot (kt+3)&3

        if (kt + 3 < nkt) load_stage((kt + 3) & 3, kt + 3);
        asm volatile("cp.async.commit_group;\n");

        #pragma unroll
        for (int kb = 0; kb < 2; kb++) {
            uint4 Aq[2], Bq[2];
            #pragma unroll
            for (int mi = 0; mi < 2; mi++)
                Aq[mi] = sm[cur][kb * 128 + (wm * 2 + mi) * 32 + lane];
            #pragma unroll
            for (int nj = 0; nj < 2; nj++)
                Bq[nj] = sm[cur][256 + kb * 256 + (wn * 2 + nj) * 32 + lane];

            #pragma unroll
            for (int mi = 0; mi < 2; mi++) {
                mma_f16(acc[mi][0], Aq[mi].x, Aq[mi].z, Aq[mi].y, Aq[mi].w, Bq[0].x, Bq[0].y);
                mma_f16(acc[mi][1], Aq[mi].x, Aq[mi].z, Aq[mi].y, Aq[mi].w, Bq[0].z, Bq[0].w);
                mma_f16(acc[mi][2], Aq[mi].x, Aq[mi].z, Aq[mi].y, Aq[mi].w, Bq[1].x, Bq[1].y);
                mma_f16(acc[mi][3], Aq[mi].x, Aq[mi].z, Aq[mi].y, Aq[mi].w, Bq[1].z, Bq[1].w);
            }
        }
    }

    // Epilogue
    if (EPI_F16) {
        __half* Ch = (__half*)Cout;   // blocked layout, no batch (proj only)
        #pragma unroll
        for (int mi = 0; mi < 2; mi++) {
            #pragma unroll
            for (int nt = 0; nt < 4; nt++) {
                const int r0 = m0 + wm * 32 + mi * 16 + (lane >> 2);
                const int c0 = n0 + wn * 32 + nt * 8 + 2 * (lane & 3);
                const long off = blk_off(r0, c0, ldc);
                *(uint32_t*)(Ch + off)     = pack2(acc[mi][nt][0], acc[mi][nt][1]);
                *(uint32_t*)(Ch + off + 4) = pack2(acc[mi][nt][2], acc[mi][nt][3]);
            }
        }
    } else {
        float* Cf = (float*)Cout + (long)blockIdx.z * sC;
        #pragma unroll
        for (int mi = 0; mi < 2; mi++) {
            #pragma unroll
            for (int nt = 0; nt < 4; nt++) {
                const int r0 = m0 + wm * 32 + mi * 16 + (lane >> 2);
                const int c0 = n0 + wn * 32 + nt * 8 + 2 * (lane & 3);
                *(float2*)&Cf[(long)r0 * ldc + c0] =
                    make_float2(acc[mi][nt][0], acc[mi][nt][1]);
                *(float2*)&Cf[(long)(r0 + 8) * ldc + c0] =
                    make_float2(acc[mi][nt][2], acc[mi][nt][3]);
            }
        }
    }
}

// ---------------------------------------------------------------------------
// Causal row softmax: fp32 scores (row-major) -> fp16 probs (blocked).
// Logits s/32.  Zero-fills [len, ceil64(len)) so the PV GEMM (Keff=m0+64)
// reads only valid data.
// ---------------------------------------------------------------------------
__global__ void __launch_bounds__(256)
softmax_k(const float* __restrict__ S, __half* __restrict__ Ph)
{
    const int row = blockIdx.x;
    const int b = row >> 11;
    const int i = row & 2047;
    const float* p = S + ((long)b * Sq + i) * Sq;
    __half* ph = Ph + (long)b * Sq * Sq;
    const int tid = threadIdx.x;
    const int len = i + 1;
    const int lenPad = (len + 63) & ~63;
    const int npairs = lenPad >> 1;

    float e[4][2];
    #pragma unroll
    for (int k = 0; k < 4; k++) {
        const int j2 = tid + 256 * k;
        if (j2 < npairs) {
            const float2 v = *(const float2*)(p + 2 * j2);
            const int j = 2 * j2;
            e[k][0] = (j     < len) ? v.x : -3.4e38f;
            e[k][1] = (j + 1 < len) ? v.y : -3.4e38f;
        } else {
            e[k][0] = e[k][1] = -3.4e38f;
        }
    }

    float mx = -3.4e38f;
    #pragma unroll
    for (int k = 0; k < 4; k++) mx = fmaxf(mx, fmaxf(e[k][0], e[k][1]));
    mx = warp_max(mx);

    __shared__ float red[8];
    if ((tid & 31) == 0) red[tid >> 5] = mx;
    __syncthreads();
    mx = red[0];
    #pragma unroll
    for (int w = 1; w < 8; w++) mx = fmaxf(mx, red[w]);

    float s = 0.f;
    #pragma unroll
    for (int k = 0; k < 4; k++) {
        e[k][0] = __expf((e[k][0] - mx) * 0.03125f);
        e[k][1] = __expf((e[k][1] - mx) * 0.03125f);
        s += e[k][0] + e[k][1];
    }
    s = warp_sum(s);
    __syncthreads();
    if ((tid & 31) == 0) red[tid >> 5] = s;
    __syncthreads();
    float tot = 0.f;
    #pragma unroll
    for (int w = 0; w < 8; w++) tot += red[w];
    const float inv = 1.0f / tot;

    #pragma unroll
    for (int k = 0; k < 4; k++) {
        const int j2 = tid + 256 * k;
        if (j2 < npairs) {
            const int j = 2 * j2;
            *(uint32_t*)(ph + blk_off(i, j, Sq)) =
                pack2(e[k][0] * inv, e[k][1] * inv);
        }
    }
}

// ---------------------------------------------------------------------------
extern "C" void kernel_launch(void* const* d_in, const int* in_sizes, int n_in,
                              void* d_out, int out_size)
{
    const float* x  = (const float*)d_in[0];
    const float* Wq = (const float*)d_in[1];
    const float* Wk = (const float*)d_in[2];
    const float* Wv = (const float*)d_in[3];
    float* out = (float*)d_out;

    __half *Xh, *WqT, *WkT, *WvT, *Qh, *Kh, *Vt, *Ph;
    float *V, *Sb;
    cudaGetSymbolAddress((void**)&Xh,  g_Xh);
    cudaGetSymbolAddress((void**)&WqT, g_WqT);
    cudaGetSymbolAddress((void**)&WkT, g_WkT);
    cudaGetSymbolAddress((void**)&WvT, g_WvT);
    cudaGetSymbolAddress((void**)&Qh,  g_Qh);
    cudaGetSymbolAddress((void**)&Kh,  g_Kh);
    cudaGetSymbolAddress((void**)&V,   g_V);
    cudaGetSymbolAddress((void**)&Vt,  g_Vt);
    cudaGetSymbolAddress((void**)&Sb,  g_S);
    cudaGetSymbolAddress((void**)&Ph,  g_Ph);

    const int M = Bsz * Sq;   // 8192

    // 0) pack x (row-major fp32 -> blocked fp16); pack W^T (transpose+blocked)
    {
        const long nchunks = (long)M * Dm / 8;    // 16B chunks (8 halves each)
        pack_rm<<<(int)((nchunks + 255) / 256), 256>>>(x, Xh, Dm, nchunks);
        dim3 tb(32, 8);
        dim3 gw(Dm / 32, Dm / 32, 1);
        pack_t<<<gw, tb>>>(Wq, WqT, Dm, Dm);
        pack_t<<<gw, tb>>>(Wk, WkT, Dm, Dm);
        pack_t<<<gw, tb>>>(Wv, WvT, Dm, Dm);
    }

    // 1) Projections: Q,K -> fp16 blocked directly; V -> fp32 row-major
    {
        dim3 grid(Dm / 128, M / 64, 1);
        hgemm<false, false, true ><<<grid, 256>>>(Xh, WqT, Qh, Dm, Dm, 0, 0, 0);
        hgemm<false, false, true ><<<grid, 256>>>(Xh, WkT, Kh, Dm, Dm, 0, 0, 0);
        hgemm<false, false, false><<<grid, 256>>>(Xh, WvT, V,  Dm, Dm, 0, 0, 0);
    }

    // 2) Scores: S_b = Q_b K_b^T (causal-skip), fp32 row-major out
    {
        dim3 grid(Sq / 128, Sq / 64, Bsz);
        hgemm<true, false, false><<<grid, 256>>>(
            Qh, Kh, Sb, Dm, Sq,
            (long)Sq * Dm, (long)Sq * Dm, (long)Sq * Sq);
    }

    // 3) Softmax -> fp16 blocked probs
    softmax_k<<<Bsz * Sq, 256>>>(Sb, Ph);

    // 4) V^T pack, then O = P Vt^T (causal K-limit), fp32 out
    {
        dim3 tb(32, 8);
        pack_t<<<dim3(Sq / 32, Dm / 32, Bsz), tb>>>(V, Vt, Sq, Dm);
        dim3 grid(Dm / 128, Sq / 64, Bsz);
        hgemm<false, true, false><<<grid, 256>>>(
            Ph, Vt, out, Sq, Dm,
            (long)Sq * Sq, (long)Sq * Dm, (long)Sq * Dm);
    }

    (void)in_sizes; (void)n_in; (void)out_size;
}

// round 10
// speedup vs baseline: 1.1797x; 1.0298x over previous
#include <cuda_runtime.h>
#include <cuda_fp16.h>
#include <cstdint>

// Problem constants
constexpr int Bsz = 4;
constexpr int Sq  = 2048;
constexpr int Dm  = 1024;

// Scratch (device globals; no allocation allowed).
// "blocked" fp16 layout: matrix [R x K] split into 16x16 blocks, block
// (br,bk) stored at (br*(K/16)+bk)*256 halves; inside a block, 16B chunk
// (g,q), g=0..7,q=0..3 (chunk idx = g*4+q), holds halves
//   x: [row g,   k 2q,2q+1]   y: [row g,   k 2q+8,2q+9]
//   z: [row g+8, k 2q,2q+1]   w: [row g+8, k 2q+8,2q+9]
// One LDS.128 = one full m16n8k16 A-fragment (regs x,z,y,w) or two
// B-fragments (n=g via x,y and n=g+8 via z,w).
__device__ __half g_Xh [(long)Bsz * Sq * Dm];
__device__ __half g_WqT[(long)Dm * Dm];
__device__ __half g_WkT[(long)Dm * Dm];
__device__ __half g_WvT[(long)Dm * Dm];
__device__ __half g_Qh [(long)Bsz * Sq * Dm];
__device__ __half g_Kh [(long)Bsz * Sq * Dm];
__device__ __half g_Vt [(long)Bsz * Sq * Dm];   // V^T per batch, blocked
__device__ float  g_S  [(long)Bsz * Sq * Sq];   // fp32 scores, row-major
__device__ __half g_Ph [(long)Bsz * Sq * Sq];   // fp16 probs, blocked

// ---------------------------------------------------------------------------
// helpers
// ---------------------------------------------------------------------------
__device__ __forceinline__ void cp16(void* s, const void* g) {
    uint32_t sa = (uint32_t)__cvta_generic_to_shared(s);
    asm volatile("cp.async.cg.shared.global [%0], [%1], 16;\n" :: "r"(sa), "l"(g));
}

__device__ __forceinline__ void mma_f16(float* d,
    uint32_t a0, uint32_t a1, uint32_t a2, uint32_t a3,
    uint32_t b0, uint32_t b1) {
    asm volatile(
        "mma.sync.aligned.m16n8k16.row.col.f32.f16.f16.f32 "
        "{%0,%1,%2,%3},{%4,%5,%6,%7},{%8,%9},{%0,%1,%2,%3};"
        : "+f"(d[0]), "+f"(d[1]), "+f"(d[2]), "+f"(d[3])
        : "r"(a0), "r"(a1), "r"(a2), "r"(a3), "r"(b0), "r"(b1));
}

__device__ __forceinline__ uint32_t pack2(float a, float b) {
    __half2 h = __floats2half2_rn(a, b);
    return *(uint32_t*)&h;
}

__device__ __forceinline__ float warp_max(float v) {
    #pragma unroll
    for (int o = 16; o; o >>= 1) v = fmaxf(v, __shfl_xor_sync(0xFFFFFFFFu, v, o));
    return v;
}
__device__ __forceinline__ float warp_sum(float v) {
    #pragma unroll
    for (int o = 16; o; o >>= 1) v += __shfl_xor_sync(0xFFFFFFFFu, v, o);
    return v;
}

// half offset of element (r, k) inside blocked [R x K] matrix (Kd = K size).
// For even k this is the start of the (k, k+1) pair.
__device__ __forceinline__ long blk_off(int r, int k, int Kd) {
    return ((long)(r >> 4) * (Kd >> 4) + (k >> 4)) * 256
         + ((r & 7) * 4 + ((k >> 1) & 3)) * 8
         + ((r >> 3) & 1) * 4 + ((k >> 3) & 1) * 2 + (k & 1);
}

// ---------------------------------------------------------------------------
// Pack fp32 row-major [R x Kd] -> fp16 blocked.  One thread produces TWO
// adjacent 16B chunks from 4 coalesced float4 loads.  nth = R*Kd/16.
// ---------------------------------------------------------------------------
__global__ void __launch_bounds__(256)
pack_rm(const float* __restrict__ in, __half* __restrict__ out,
        int Kd, long nth)
{
    long t = (long)blockIdx.x * blockDim.x + threadIdx.x;
    if (t >= nth) return;
    const long blk = t >> 4;
    const int sub = (int)(t & 15);
    const int g = sub >> 1, qh = sub & 1;
    const int Kb = Kd >> 4;
    const int rb = (int)(blk / Kb), kb = (int)(blk % Kb);
    const int r = rb * 16 + g;
    const float* p = in + (long)r * Kd + kb * 16 + qh * 4;
    float4 lo  = *(const float4*)p;
    float4 lo8 = *(const float4*)(p + 8);
    float4 hi  = *(const float4*)(p + (long)8 * Kd);
    float4 hi8 = *(const float4*)(p + (long)8 * Kd + 8);
    uint4 u0, u1;
    u0.x = pack2(lo.x, lo.y);   u0.y = pack2(lo8.x, lo8.y);
    u0.z = pack2(hi.x, hi.y);   u0.w = pack2(hi8.x, hi8.y);
    u1.x = pack2(lo.z, lo.w);   u1.y = pack2(lo8.z, lo8.w);
    u1.z = pack2(hi.z, hi.w);   u1.w = pack2(hi8.z, hi8.w);
    uint4* o = (uint4*)out + blk * 32 + g * 4 + 2 * qh;
    o[0] = u0;
    o[1] = u1;
}

// ---------------------------------------------------------------------------
// Transpose fp32 [Rin x Cin] -> fp16 blocked [Cin x Rin].  (weights only)
// ---------------------------------------------------------------------------
__global__ void __launch_bounds__(256)
pack_t(const float* __restrict__ in, __half* __restrict__ out, int Rin, int Cin)
{
    __shared__ float t[32][33];
    const int r0 = blockIdx.x * 32, c0 = blockIdx.y * 32;
    const int x = threadIdx.x, y = threadIdx.y;     // (32, 8)
    #pragma unroll
    for (int i = 0; i < 32; i += 8)
        t[y + i][x] = in[(long)(r0 + y + i) * Cin + c0 + x];
    __syncthreads();

    const int tid = y * 32 + x;
    if (tid < 128) {
        const int blk = tid >> 5, idx = tid & 31;
        const int brl = blk >> 1, bkl = blk & 1;
        const int g = idx >> 2, q = idx & 3;
        const int E  = 16 * brl + g;       // out-row within 32 (orig col)
        const int S0 = 16 * bkl + 2 * q;   // out-k within 32 (orig row)
        uint4 u;
        u.x = pack2(t[S0][E],         t[S0 + 1][E]);
        u.y = pack2(t[S0 + 8][E],     t[S0 + 9][E]);
        u.z = pack2(t[S0][E + 8],     t[S0 + 1][E + 8]);
        u.w = pack2(t[S0 + 8][E + 8], t[S0 + 9][E + 8]);
        const long chunk =
            ((long)((c0 >> 4) + brl) * (Rin >> 4) + (r0 >> 4) + bkl) * 32 + idx;
        ((uint4*)out)[chunk] = u;
    }
}

// ---------------------------------------------------------------------------
// FP16 mma.sync GEMM on blocked operands:  C[M,N] = A[M,K] * B[N,K]^T
// CTA 64(M) x 128(N), 8 warps (2x4), warp tile 32x32.
// K-chunk 32 per pipeline stage (two 16-K blocks), 4 stages, ONE
// __syncthreads per chunk.  Per iter per warp: 8 LDS.128 + 16 HMMA.
// EPI: 0 = fp32 row-major (batched); 1 = fp16 blocked (no batch);
//      2 = fp16 blocked TRANSPOSED per batch of 2048 rows (V -> Vt).
// ---------------------------------------------------------------------------
template <bool CAUSAL_SKIP, bool KLIMIT, int EPI>
__global__ void __launch_bounds__(256)
hgemm(const __half* __restrict__ A, const __half* __restrict__ B, void* Cout,
      int Kd, int ldc, long sA, long sB, long sC)
{
    const int m0 = blockIdx.y * 64;
    const int n0 = blockIdx.x * 128;
    if (CAUSAL_SKIP && n0 > m0 + 63) return;

    A += (long)blockIdx.z * sA;
    B += (long)blockIdx.z * sB;

    const int Keff = KLIMIT ? min(Kd, m0 + 64) : Kd;
    const int nkt  = Keff >> 5;          // K-chunks of 32
    const int Kb   = Kd >> 4;            // 16-K blocks per row

    __shared__ uint4 sm[4][768];         // 48 KB

    const int tid  = threadIdx.x;
    const int warp = tid >> 5;
    const int lane = tid & 31;
    const int wm   = warp >> 2;          // 0..1
    const int wn   = warp & 3;           // 0..3

    // A loader: 256 chunks, 1/thread
    const int akb = tid >> 7;            // 0..1
    const int amb = (tid >> 5) & 3;      // 0..3
    const uint4* ag = (const uint4*)A + ((long)((m0 >> 4) + amb) * Kb + akb) * 32 + lane;
    const int asmi = akb * 128 + amb * 32 + lane;
    // B loader: 512 chunks, 2/thread (kb = i, nb = warp)
    const uint4* bg0 = (const uint4*)B + ((long)((n0 >> 4) + warp) * Kb + 0) * 32 + lane;
    const uint4* bg1 = (const uint4*)B + ((long)((n0 >> 4) + warp) * Kb + 1) * 32 + lane;
    const int bsmi0 = 256 +       warp * 32 + lane;
    const int bsmi1 = 256 + 256 + warp * 32 + lane;

    auto load_stage = [&](int st, int kt) {
        const long koff = (long)kt * 64;   // 2 blocks of 32 chunks
        cp16(&sm[st][asmi],  ag  + koff);
        cp16(&sm[st][bsmi0], bg0 + koff);
        cp16(&sm[st][bsmi1], bg1 + koff);
    };

    #pragma unroll
    for (int s = 0; s < 3; s++) {
        if (s < nkt) load_stage(s, s);
        asm volatile("cp.async.commit_group;\n");
    }

    float acc[2][4][4] = {};

    for (int kt = 0; kt < nkt; ++kt) {
        const int cur = kt & 3;
        asm volatile("cp.async.wait_group 2;\n");
        __syncthreads();   // data ready + all warps done reading slot (kt+3)&3

        if (kt + 3 < nkt) load_stage((kt + 3) & 3, kt + 3);
        asm volatile("cp.async.commit_group;\n");

        #pragma unroll
        for (int kb = 0; kb < 2; kb++) {
            uint4 Aq[2], Bq[2];
            #pragma unroll
            for (int mi = 0; mi < 2; mi++)
                Aq[mi] = sm[cur][kb * 128 + (wm * 2 + mi) * 32 + lane];
            #pragma unroll
            for (int nj = 0; nj < 2; nj++)
                Bq[nj] = sm[cur][256 + kb * 256 + (wn * 2 + nj) * 32 + lane];

            #pragma unroll
            for (int mi = 0; mi < 2; mi++) {
                mma_f16(acc[mi][0], Aq[mi].x, Aq[mi].z, Aq[mi].y, Aq[mi].w, Bq[0].x, Bq[0].y);
                mma_f16(acc[mi][1], Aq[mi].x, Aq[mi].z, Aq[mi].y, Aq[mi].w, Bq[0].z, Bq[0].w);
                mma_f16(acc[mi][2], Aq[mi].x, Aq[mi].z, Aq[mi].y, Aq[mi].w, Bq[1].x, Bq[1].y);
                mma_f16(acc[mi][3], Aq[mi].x, Aq[mi].z, Aq[mi].y, Aq[mi].w, Bq[1].z, Bq[1].w);
            }
        }
    }

    // Epilogue
    #pragma unroll
    for (int mi = 0; mi < 2; mi++) {
        #pragma unroll
        for (int nt = 0; nt < 4; nt++) {
            const int r0 = m0 + wm * 32 + mi * 16 + (lane >> 2);
            const int c0 = n0 + wn * 32 + nt * 8 + 2 * (lane & 3);
            if (EPI == 1) {
                __half* Ch = (__half*)Cout;
                const long off = blk_off(r0, c0, ldc);
                *(uint32_t*)(Ch + off)     = pack2(acc[mi][nt][0], acc[mi][nt][1]);
                *(uint32_t*)(Ch + off + 4) = pack2(acc[mi][nt][2], acc[mi][nt][3]);
            } else if (EPI == 2) {
                // C value (r0,c) -> Vt[batch][row=c][k=r0&2047], blocked
                const int b   = r0 >> 11;
                const int rb0 = r0 & 2047;
                __half* Vb = (__half*)Cout + (long)b * Sq * Dm;
                Vb[blk_off(c0,     rb0,     Sq)] = __float2half_rn(acc[mi][nt][0]);
                Vb[blk_off(c0 + 1, rb0,     Sq)] = __float2half_rn(acc[mi][nt][1]);
                Vb[blk_off(c0,     rb0 + 8, Sq)] = __float2half_rn(acc[mi][nt][2]);
                Vb[blk_off(c0 + 1, rb0 + 8, Sq)] = __float2half_rn(acc[mi][nt][3]);
            } else {
                float* Cf = (float*)Cout + (long)blockIdx.z * sC;
                *(float2*)&Cf[(long)r0 * ldc + c0] =
                    make_float2(acc[mi][nt][0], acc[mi][nt][1]);
                *(float2*)&Cf[(long)(r0 + 8) * ldc + c0] =
                    make_float2(acc[mi][nt][2], acc[mi][nt][3]);
            }
        }
    }
}

// ---------------------------------------------------------------------------
// Causal row softmax: fp32 scores (row-major) -> fp16 probs (blocked).
// Logits s/32.  Zero-fills [len, ceil64(len)); PV reads exactly that far.
// float4 loads; up to 2 quads per thread.
// ---------------------------------------------------------------------------
__global__ void __launch_bounds__(256)
softmax_k(const float* __restrict__ S, __half* __restrict__ Ph)
{
    const int row = blockIdx.x;
    const int b = row >> 11;
    const int i = row & 2047;
    const float* p = S + ((long)b * Sq + i) * Sq;
    __half* ph = Ph + (long)b * Sq * Sq;
    const int tid = threadIdx.x;
    const int len = i + 1;
    const int lenPad = (len + 63) & ~63;
    const int nquads = lenPad >> 2;

    float e[2][4];
    #pragma unroll
    for (int k = 0; k < 2; k++) {
        const int j4 = tid + 256 * k;
        if (j4 < nquads) {
            const float4 v = ((const float4*)p)[j4];
            const int j = 4 * j4;
            e[k][0] = (j     < len) ? v.x : -3.4e38f;
            e[k][1] = (j + 1 < len) ? v.y : -3.4e38f;
            e[k][2] = (j + 2 < len) ? v.z : -3.4e38f;
            e[k][3] = (j + 3 < len) ? v.w : -3.4e38f;
        } else {
            e[k][0] = e[k][1] = e[k][2] = e[k][3] = -3.4e38f;
        }
    }

    float mx = -3.4e38f;
    #pragma unroll
    for (int k = 0; k < 2; k++)
        #pragma unroll
        for (int u = 0; u < 4; u++) mx = fmaxf(mx, e[k][u]);
    mx = warp_max(mx);

    __shared__ float red[8];
    if ((tid & 31) == 0) red[tid >> 5] = mx;
    __syncthreads();
    mx = red[0];
    #pragma unroll
    for (int w = 1; w < 8; w++) mx = fmaxf(mx, red[w]);

    float s = 0.f;
    #pragma unroll
    for (int k = 0; k < 2; k++)
        #pragma unroll
        for (int u = 0; u < 4; u++) {
            e[k][u] = __expf((e[k][u] - mx) * 0.03125f);
            s += e[k][u];
        }
    s = warp_sum(s);
    __syncthreads();
    if ((tid & 31) == 0) red[tid >> 5] = s;
    __syncthreads();
    float tot = 0.f;
    #pragma unroll
    for (int w = 0; w < 8; w++) tot += red[w];
    const float inv = 1.0f / tot;

    #pragma unroll
    for (int k = 0; k < 2; k++) {
        const int j4 = tid + 256 * k;
        if (j4 < nquads) {
            const int j = 4 * j4;
            *(uint32_t*)(ph + blk_off(i, j, Sq)) =
                pack2(e[k][0] * inv, e[k][1] * inv);
            *(uint32_t*)(ph + blk_off(i, j + 2, Sq)) =
                pack2(e[k][2] * inv, e[k][3] * inv);
        }
    }
}

// ---------------------------------------------------------------------------
extern "C" void kernel_launch(void* const* d_in, const int* in_sizes, int n_in,
                              void* d_out, int out_size)
{
    const float* x  = (const float*)d_in[0];
    const float* Wq = (const float*)d_in[1];
    const float* Wk = (const float*)d_in[2];
    const float* Wv = (const float*)d_in[3];
    float* out = (float*)d_out;

    __half *Xh, *WqT, *WkT, *WvT, *Qh, *Kh, *Vt, *Ph;
    float *Sb;
    cudaGetSymbolAddress((void**)&Xh,  g_Xh);
    cudaGetSymbolAddress((void**)&WqT, g_WqT);
    cudaGetSymbolAddress((void**)&WkT, g_WkT);
    cudaGetSymbolAddress((void**)&WvT, g_WvT);
    cudaGetSymbolAddress((void**)&Qh,  g_Qh);
    cudaGetSymbolAddress((void**)&Kh,  g_Kh);
    cudaGetSymbolAddress((void**)&Vt,  g_Vt);
    cudaGetSymbolAddress((void**)&Sb,  g_S);
    cudaGetSymbolAddress((void**)&Ph,  g_Ph);

    const int M = Bsz * Sq;   // 8192

    // 0) pack x (fp32 rm -> fp16 blocked, 2 chunks/thread); pack W^T
    {
        const long nth = (long)M * Dm / 16;
        pack_rm<<<(int)((nth + 255) / 256), 256>>>(x, Xh, Dm, nth);
        dim3 tb(32, 8);
        dim3 gw(Dm / 32, Dm / 32, 1);
        pack_t<<<gw, tb>>>(Wq, WqT, Dm, Dm);
        pack_t<<<gw, tb>>>(Wk, WkT, Dm, Dm);
        pack_t<<<gw, tb>>>(Wv, WvT, Dm, Dm);
    }

    // 1) Projections: Q,K -> fp16 blocked; V -> Vt (transposed blocked) direct
    {
        dim3 grid(Dm / 128, M / 64, 1);
        hgemm<false, false, 1><<<grid, 256>>>(Xh, WqT, Qh, Dm, Dm, 0, 0, 0);
        hgemm<false, false, 1><<<grid, 256>>>(Xh, WkT, Kh, Dm, Dm, 0, 0, 0);
        hgemm<false, false, 2><<<grid, 256>>>(Xh, WvT, Vt, Dm, Dm, 0, 0, 0);
    }

    // 2) Scores: S_b = Q_b K_b^T (causal-skip), fp32 row-major out
    {
        dim3 grid(Sq / 128, Sq / 64, Bsz);
        hgemm<true, false, 0><<<grid, 256>>>(
            Qh, Kh, Sb, Dm, Sq,
            (long)Sq * Dm, (long)Sq * Dm, (long)Sq * Sq);
    }

    // 3) Softmax -> fp16 blocked probs
    softmax_k<<<Bsz * Sq, 256>>>(Sb, Ph);

    // 4) O = P Vt^T (causal K-limit), fp32 out
    {
        dim3 grid(Dm / 128, Sq / 64, Bsz);
        hgemm<false, true, 0><<<grid, 256>>>(
            Ph, Vt, out, Sq, Dm,
            (long)Sq * Sq, (long)Sq * Dm, (long)Sq * Dm);
    }

    (void)in_sizes; (void)n_in; (void)out_size;
}

// round 11
// speedup vs baseline: 1.2199x; 1.0340x over previous
#include <cuda_runtime.h>
#include <cuda_fp16.h>
#include <cstdint>

// Problem constants
constexpr int Bsz = 4;
constexpr int Sq  = 2048;
constexpr int Dm  = 1024;

// Scratch (device globals; no allocation allowed).
// "blocked" fp16 layout: matrix [R x K] split into 16x16 blocks, block
// (br,bk) stored at (br*(K/16)+bk)*256 halves; inside a block, 16B chunk
// (g,q), g=0..7,q=0..3 (chunk idx = g*4+q), holds halves
//   x: [row g,   k 2q,2q+1]   y: [row g,   k 2q+8,2q+9]
//   z: [row g+8, k 2q,2q+1]   w: [row g+8, k 2q+8,2q+9]
// One LDS.128 = one full m16n8k16 A-fragment (regs x,z,y,w) or two
// B-fragments (n=g via x,y and n=g+8 via z,w).
__device__ __half g_Xh [(long)Bsz * Sq * Dm];
__device__ __half g_WqT[(long)Dm * Dm];
__device__ __half g_WkT[(long)Dm * Dm];
__device__ __half g_WvT[(long)Dm * Dm];
__device__ __half g_Qh [(long)Bsz * Sq * Dm];
__device__ __half g_Kh [(long)Bsz * Sq * Dm];
__device__ __half g_Vt [(long)Bsz * Sq * Dm];   // V^T per batch, blocked
__device__ float  g_S  [(long)Bsz * Sq * Sq];   // fp32 scores, row-major
__device__ __half g_Ph [(long)Bsz * Sq * Sq];   // fp16 probs, blocked

// ---------------------------------------------------------------------------
// helpers
// ---------------------------------------------------------------------------
__device__ __forceinline__ void cp16(void* s, const void* g) {
    uint32_t sa = (uint32_t)__cvta_generic_to_shared(s);
    asm volatile("cp.async.cg.shared.global [%0], [%1], 16;\n" :: "r"(sa), "l"(g));
}

__device__ __forceinline__ void mma_f16(float* d,
    uint32_t a0, uint32_t a1, uint32_t a2, uint32_t a3,
    uint32_t b0, uint32_t b1) {
    asm volatile(
        "mma.sync.aligned.m16n8k16.row.col.f32.f16.f16.f32 "
        "{%0,%1,%2,%3},{%4,%5,%6,%7},{%8,%9},{%0,%1,%2,%3};"
        : "+f"(d[0]), "+f"(d[1]), "+f"(d[2]), "+f"(d[3])
        : "r"(a0), "r"(a1), "r"(a2), "r"(a3), "r"(b0), "r"(b1));
}

__device__ __forceinline__ uint32_t pack2(float a, float b) {
    __half2 h = __floats2half2_rn(a, b);
    return *(uint32_t*)&h;
}

__device__ __forceinline__ float warp_max(float v) {
    #pragma unroll
    for (int o = 16; o; o >>= 1) v = fmaxf(v, __shfl_xor_sync(0xFFFFFFFFu, v, o));
    return v;
}
__device__ __forceinline__ float warp_sum(float v) {
    #pragma unroll
    for (int o = 16; o; o >>= 1) v += __shfl_xor_sync(0xFFFFFFFFu, v, o);
    return v;
}

// half offset of element (r, k) inside blocked [R x K] matrix (Kd = K size).
// For even k this is the start of the (k, k+1) pair.
__device__ __forceinline__ long blk_off(int r, int k, int Kd) {
    return ((long)(r >> 4) * (Kd >> 4) + (k >> 4)) * 256
         + ((r & 7) * 4 + ((k >> 1) & 3)) * 8
         + ((r >> 3) & 1) * 4 + ((k >> 3) & 1) * 2 + (k & 1);
}

// ---------------------------------------------------------------------------
// Pack fp32 row-major [R x Kd] -> fp16 blocked.  One thread produces TWO
// adjacent 16B chunks from 4 coalesced float4 loads.  nth = R*Kd/16.
// ---------------------------------------------------------------------------
__global__ void __launch_bounds__(256)
pack_rm(const float* __restrict__ in, __half* __restrict__ out,
        int Kd, long nth)
{
    long t = (long)blockIdx.x * blockDim.x + threadIdx.x;
    if (t >= nth) return;
    const long blk = t >> 4;
    const int sub = (int)(t & 15);
    const int g = sub >> 1, qh = sub & 1;
    const int Kb = Kd >> 4;
    const int rb = (int)(blk / Kb), kb = (int)(blk % Kb);
    const int r = rb * 16 + g;
    const float* p = in + (long)r * Kd + kb * 16 + qh * 4;
    float4 lo  = *(const float4*)p;
    float4 lo8 = *(const float4*)(p + 8);
    float4 hi  = *(const float4*)(p + (long)8 * Kd);
    float4 hi8 = *(const float4*)(p + (long)8 * Kd + 8);
    uint4 u0, u1;
    u0.x = pack2(lo.x, lo.y);   u0.y = pack2(lo8.x, lo8.y);
    u0.z = pack2(hi.x, hi.y);   u0.w = pack2(hi8.x, hi8.y);
    u1.x = pack2(lo.z, lo.w);   u1.y = pack2(lo8.z, lo8.w);
    u1.z = pack2(hi.z, hi.w);   u1.w = pack2(hi8.z, hi8.w);
    uint4* o = (uint4*)out + blk * 32 + g * 4 + 2 * qh;
    o[0] = u0;
    o[1] = u1;
}

// ---------------------------------------------------------------------------
// Transpose fp32 [Rin x Cin] -> fp16 blocked [Cin x Rin].  (weights only)
// ---------------------------------------------------------------------------
__global__ void __launch_bounds__(256)
pack_t(const float* __restrict__ in, __half* __restrict__ out, int Rin, int Cin)
{
    __shared__ float t[32][33];
    const int r0 = blockIdx.x * 32, c0 = blockIdx.y * 32;
    const int x = threadIdx.x, y = threadIdx.y;     // (32, 8)
    #pragma unroll
    for (int i = 0; i < 32; i += 8)
        t[y + i][x] = in[(long)(r0 + y + i) * Cin + c0 + x];
    __syncthreads();

    const int tid = y * 32 + x;
    if (tid < 128) {
        const int blk = tid >> 5, idx = tid & 31;
        const int brl = blk >> 1, bkl = blk & 1;
        const int g = idx >> 2, q = idx & 3;
        const int E  = 16 * brl + g;       // out-row within 32 (orig col)
        const int S0 = 16 * bkl + 2 * q;   // out-k within 32 (orig row)
        uint4 u;
        u.x = pack2(t[S0][E],         t[S0 + 1][E]);
        u.y = pack2(t[S0 + 8][E],     t[S0 + 9][E]);
        u.z = pack2(t[S0][E + 8],     t[S0 + 1][E + 8]);
        u.w = pack2(t[S0 + 8][E + 8], t[S0 + 9][E + 8]);
        const long chunk =
            ((long)((c0 >> 4) + brl) * (Rin >> 4) + (r0 >> 4) + bkl) * 32 + idx;
        ((uint4*)out)[chunk] = u;
    }
}

// ---------------------------------------------------------------------------
// FP16 mma.sync GEMM on blocked operands:  C[M,N] = A[M,K] * B[N,K]^T
// CTA 64(M) x 128(N), 8 warps (2x4), warp tile 32x32.
// K-chunk 32 per pipeline stage (two 16-K blocks), 4 stages, ONE
// __syncthreads per chunk.  Per iter per warp: 8 LDS.128 + 16 HMMA.
// __launch_bounds__(256, 3): 3 CTAs/SM (smem carveout raised host-side)
// so barrier stalls of one CTA are covered by the other two.
// EPI: 0 = fp32 row-major (batched); 1 = fp16 blocked (no batch);
//      2 = fp16 blocked TRANSPOSED per batch of 2048 rows (V -> Vt).
// ---------------------------------------------------------------------------
template <bool CAUSAL_SKIP, bool KLIMIT, int EPI>
__global__ void __launch_bounds__(256, 3)
hgemm(const __half* __restrict__ A, const __half* __restrict__ B, void* Cout,
      int Kd, int ldc, long sA, long sB, long sC)
{
    const int m0 = blockIdx.y * 64;
    const int n0 = blockIdx.x * 128;
    if (CAUSAL_SKIP && n0 > m0 + 63) return;

    A += (long)blockIdx.z * sA;
    B += (long)blockIdx.z * sB;

    const int Keff = KLIMIT ? min(Kd, m0 + 64) : Kd;
    const int nkt  = Keff >> 5;          // K-chunks of 32
    const int Kb   = Kd >> 4;            // 16-K blocks per row

    __shared__ uint4 sm[4][768];         // 48 KB

    const int tid  = threadIdx.x;
    const int warp = tid >> 5;
    const int lane = tid & 31;
    const int wm   = warp >> 2;          // 0..1
    const int wn   = warp & 3;           // 0..3

    // A loader: 256 chunks, 1/thread
    const int akb = tid >> 7;            // 0..1
    const int amb = (tid >> 5) & 3;      // 0..3
    const uint4* ag = (const uint4*)A + ((long)((m0 >> 4) + amb) * Kb + akb) * 32 + lane;
    const int asmi = akb * 128 + amb * 32 + lane;
    // B loader: 512 chunks, 2/thread (kb = i, nb = warp)
    const uint4* bg0 = (const uint4*)B + ((long)((n0 >> 4) + warp) * Kb + 0) * 32 + lane;
    const uint4* bg1 = (const uint4*)B + ((long)((n0 >> 4) + warp) * Kb + 1) * 32 + lane;
    const int bsmi0 = 256 +       warp * 32 + lane;
    const int bsmi1 = 256 + 256 + warp * 32 + lane;

    auto load_stage = [&](int st, int kt) {
        const long koff = (long)kt * 64;   // 2 blocks of 32 chunks
        cp16(&sm[st][asmi],  ag  + koff);
        cp16(&sm[st][bsmi0], bg0 + koff);
        cp16(&sm[st][bsmi1], bg1 + koff);
    };

    #pragma unroll
    for (int s = 0; s < 3; s++) {
        if (s < nkt) load_stage(s, s);
        asm volatile("cp.async.commit_group;\n");
    }

    float acc[2][4][4] = {};

    for (int kt = 0; kt < nkt; ++kt) {
        const int cur = kt & 3;
        asm volatile("cp.async.wait_group 2;\n");
        __syncthreads();   // data ready + all warps done reading slot (kt+3)&3

        if (kt + 3 < nkt) load_stage((kt + 3) & 3, kt + 3);
        asm volatile("cp.async.commit_group;\n");

        #pragma unroll
        for (int kb = 0; kb < 2; kb++) {
            uint4 Aq[2], Bq[2];
            #pragma unroll
            for (int mi = 0; mi < 2; mi++)
                Aq[mi] = sm[cur][kb * 128 + (wm * 2 + mi) * 32 + lane];
            #pragma unroll
            for (int nj = 0; nj < 2; nj++)
                Bq[nj] = sm[cur][256 + kb * 256 + (wn * 2 + nj) * 32 + lane];

            #pragma unroll
            for (int mi = 0; mi < 2; mi++) {
                mma_f16(acc[mi][0], Aq[mi].x, Aq[mi].z, Aq[mi].y, Aq[mi].w, Bq[0].x, Bq[0].y);
                mma_f16(acc[mi][1], Aq[mi].x, Aq[mi].z, Aq[mi].y, Aq[mi].w, Bq[0].z, Bq[0].w);
                mma_f16(acc[mi][2], Aq[mi].x, Aq[mi].z, Aq[mi].y, Aq[mi].w, Bq[1].x, Bq[1].y);
                mma_f16(acc[mi][3], Aq[mi].x, Aq[mi].z, Aq[mi].y, Aq[mi].w, Bq[1].z, Bq[1].w);
            }
        }
    }

    // Epilogue
    #pragma unroll
    for (int mi = 0; mi < 2; mi++) {
        #pragma unroll
        for (int nt = 0; nt < 4; nt++) {
            const int r0 = m0 + wm * 32 + mi * 16 + (lane >> 2);
            const int c0 = n0 + wn * 32 + nt * 8 + 2 * (lane & 3);
            if (EPI == 1) {
                __half* Ch = (__half*)Cout;
                const long off = blk_off(r0, c0, ldc);
                *(uint32_t*)(Ch + off)     = pack2(acc[mi][nt][0], acc[mi][nt][1]);
                *(uint32_t*)(Ch + off + 4) = pack2(acc[mi][nt][2], acc[mi][nt][3]);
            } else if (EPI == 2) {
                // C value (r0,c) -> Vt[batch][row=c][k=r0&2047], blocked
                const int b   = r0 >> 11;
                const int rb0 = r0 & 2047;
                __half* Vb = (__half*)Cout + (long)b * Sq * Dm;
                Vb[blk_off(c0,     rb0,     Sq)] = __float2half_rn(acc[mi][nt][0]);
                Vb[blk_off(c0 + 1, rb0,     Sq)] = __float2half_rn(acc[mi][nt][1]);
                Vb[blk_off(c0,     rb0 + 8, Sq)] = __float2half_rn(acc[mi][nt][2]);
                Vb[blk_off(c0 + 1, rb0 + 8, Sq)] = __float2half_rn(acc[mi][nt][3]);
            } else {
                float* Cf = (float*)Cout + (long)blockIdx.z * sC;
                *(float2*)&Cf[(long)r0 * ldc + c0] =
                    make_float2(acc[mi][nt][0], acc[mi][nt][1]);
                *(float2*)&Cf[(long)(r0 + 8) * ldc + c0] =
                    make_float2(acc[mi][nt][2], acc[mi][nt][3]);
            }
        }
    }
}

// ---------------------------------------------------------------------------
// Causal row softmax: fp32 scores (row-major) -> fp16 probs (blocked).
// Logits s/32.  Zero-fills [len, ceil64(len)); PV reads exactly that far.
// ---------------------------------------------------------------------------
__global__ void __launch_bounds__(256)
softmax_k(const float* __restrict__ S, __half* __restrict__ Ph)
{
    const int row = blockIdx.x;
    const int b = row >> 11;
    const int i = row & 2047;
    const float* p = S + ((long)b * Sq + i) * Sq;
    __half* ph = Ph + (long)b * Sq * Sq;
    const int tid = threadIdx.x;
    const int len = i + 1;
    const int lenPad = (len + 63) & ~63;
    const int nquads = lenPad >> 2;

    float e[2][4];
    #pragma unroll
    for (int k = 0; k < 2; k++) {
        const int j4 = tid + 256 * k;
        if (j4 < nquads) {
            const float4 v = ((const float4*)p)[j4];
            const int j = 4 * j4;
            e[k][0] = (j     < len) ? v.x : -3.4e38f;
            e[k][1] = (j + 1 < len) ? v.y : -3.4e38f;
            e[k][2] = (j + 2 < len) ? v.z : -3.4e38f;
            e[k][3] = (j + 3 < len) ? v.w : -3.4e38f;
        } else {
            e[k][0] = e[k][1] = e[k][2] = e[k][3] = -3.4e38f;
        }
    }

    float mx = -3.4e38f;
    #pragma unroll
    for (int k = 0; k < 2; k++)
        #pragma unroll
        for (int u = 0; u < 4; u++) mx = fmaxf(mx, e[k][u]);
    mx = warp_max(mx);

    __shared__ float red[8];
    if ((tid & 31) == 0) red[tid >> 5] = mx;
    __syncthreads();
    mx = red[0];
    #pragma unroll
    for (int w = 1; w < 8; w++) mx = fmaxf(mx, red[w]);

    float s = 0.f;
    #pragma unroll
    for (int k = 0; k < 2; k++)
        #pragma unroll
        for (int u = 0; u < 4; u++) {
            e[k][u] = __expf((e[k][u] - mx) * 0.03125f);
            s += e[k][u];
        }
    s = warp_sum(s);
    __syncthreads();
    if ((tid & 31) == 0) red[tid >> 5] = s;
    __syncthreads();
    float tot = 0.f;
    #pragma unroll
    for (int w = 0; w < 8; w++) tot += red[w];
    const float inv = 1.0f / tot;

    #pragma unroll
    for (int k = 0; k < 2; k++) {
        const int j4 = tid + 256 * k;
        if (j4 < nquads) {
            const int j = 4 * j4;
            *(uint32_t*)(ph + blk_off(i, j, Sq)) =
                pack2(e[k][0] * inv, e[k][1] * inv);
            *(uint32_t*)(ph + blk_off(i, j + 2, Sq)) =
                pack2(e[k][2] * inv, e[k][3] * inv);
        }
    }
}

// ---------------------------------------------------------------------------
extern "C" void kernel_launch(void* const* d_in, const int* in_sizes, int n_in,
                              void* d_out, int out_size)
{
    const float* x  = (const float*)d_in[0];
    const float* Wq = (const float*)d_in[1];
    const float* Wk = (const float*)d_in[2];
    const float* Wv = (const float*)d_in[3];
    float* out = (float*)d_out;

    __half *Xh, *WqT, *WkT, *WvT, *Qh, *Kh, *Vt, *Ph;
    float *Sb;
    cudaGetSymbolAddress((void**)&Xh,  g_Xh);
    cudaGetSymbolAddress((void**)&WqT, g_WqT);
    cudaGetSymbolAddress((void**)&WkT, g_WkT);
    cudaGetSymbolAddress((void**)&WvT, g_WvT);
    cudaGetSymbolAddress((void**)&Qh,  g_Qh);
    cudaGetSymbolAddress((void**)&Kh,  g_Kh);
    cudaGetSymbolAddress((void**)&Vt,  g_Vt);
    cudaGetSymbolAddress((void**)&Sb,  g_S);
    cudaGetSymbolAddress((void**)&Ph,  g_Ph);

    // Max shared-memory carveout so 3 CTAs x 48KB fit per SM
    cudaFuncSetAttribute((const void*)hgemm<false, false, 1>,
        cudaFuncAttributePreferredSharedMemoryCarveout, 100);
    cudaFuncSetAttribute((const void*)hgemm<false, false, 2>,
        cudaFuncAttributePreferredSharedMemoryCarveout, 100);
    cudaFuncSetAttribute((const void*)hgemm<true, false, 0>,
        cudaFuncAttributePreferredSharedMemoryCarveout, 100);
    cudaFuncSetAttribute((const void*)hgemm<false, true, 0>,
        cudaFuncAttributePreferredSharedMemoryCarveout, 100);

    const int M = Bsz * Sq;   // 8192

    // 0) pack x (fp32 rm -> fp16 blocked, 2 chunks/thread); pack W^T
    {
        const long nth = (long)M * Dm / 16;
        pack_rm<<<(int)((nth + 255) / 256), 256>>>(x, Xh, Dm, nth);
        dim3 tb(32, 8);
        dim3 gw(Dm / 32, Dm / 32, 1);
        pack_t<<<gw, tb>>>(Wq, WqT, Dm, Dm);
        pack_t<<<gw, tb>>>(Wk, WkT, Dm, Dm);
        pack_t<<<gw, tb>>>(Wv, WvT, Dm, Dm);
    }

    // 1) Projections: Q,K -> fp16 blocked; V -> Vt (transposed blocked) direct
    {
        dim3 grid(Dm / 128, M / 64, 1);
        hgemm<false, false, 1><<<grid, 256>>>(Xh, WqT, Qh, Dm, Dm, 0, 0, 0);
        hgemm<false, false, 1><<<grid, 256>>>(Xh, WkT, Kh, Dm, Dm, 0, 0, 0);
        hgemm<false, false, 2><<<grid, 256>>>(Xh, WvT, Vt, Dm, Dm, 0, 0, 0);
    }

    // 2) Scores: S_b = Q_b K_b^T (causal-skip), fp32 row-major out
    {
        dim3 grid(Sq / 128, Sq / 64, Bsz);
        hgemm<true, false, 0><<<grid, 256>>>(
            Qh, Kh, Sb, Dm, Sq,
            (long)Sq * Dm, (long)Sq * Dm, (long)Sq * Sq);
    }

    // 3) Softmax -> fp16 blocked probs
    softmax_k<<<Bsz * Sq, 256>>>(Sb, Ph);

    // 4) O = P Vt^T (causal K-limit), fp32 out
    {
        dim3 grid(Dm / 128, Sq / 64, Bsz);
        hgemm<false, true, 0><<<grid, 256>>>(
            Ph, Vt, out, Sq, Dm,
            (long)Sq * Sq, (long)Sq * Dm, (long)Sq * Dm);
    }

    (void)in_sizes; (void)n_in; (void)out_size;
}

// round 12
// speedup vs baseline: 1.3655x; 1.1194x over previous
#include <cuda_runtime.h>
#include <cuda_fp16.h>
#include <cstdint>

// Problem constants
constexpr int Bsz = 4;
constexpr int Sq  = 2048;
constexpr int Dm  = 1024;

// Scratch (device globals; no allocation allowed).
// "blocked" fp16 layout: matrix [R x K] split into 16x16 blocks, block
// (br,bk) stored at (br*(K/16)+bk)*256 halves; inside a block, 16B chunk
// (g,q), g=0..7,q=0..3 (chunk idx = g*4+q), holds halves
//   x: [row g,   k 2q,2q+1]   y: [row g,   k 2q+8,2q+9]
//   z: [row g+8, k 2q,2q+1]   w: [row g+8, k 2q+8,2q+9]
// One LDS.128 = one full m16n8k16 A-fragment (regs x,z,y,w) or two
// B-fragments (n=g via x,y and n=g+8 via z,w).
__device__ __half g_Xh  [(long)Bsz * Sq * Dm];
__device__ __half g_Wcat[(long)3 * Dm * Dm];    // WqT | WkT | WvT (row-concat)
__device__ __half g_Qh  [(long)Bsz * Sq * Dm];
__device__ __half g_Kh  [(long)Bsz * Sq * Dm];
__device__ __half g_Vt  [(long)Bsz * Sq * Dm];  // V^T per batch, blocked
__device__ float  g_S   [(long)Bsz * Sq * Sq];  // fp32 scores, row-major
__device__ __half g_Ph  [(long)Bsz * Sq * Sq];  // fp16 probs, blocked

// ---------------------------------------------------------------------------
// helpers
// ---------------------------------------------------------------------------
__device__ __forceinline__ void cp16(void* s, const void* g) {
    uint32_t sa = (uint32_t)__cvta_generic_to_shared(s);
    asm volatile("cp.async.cg.shared.global [%0], [%1], 16;\n" :: "r"(sa), "l"(g));
}

__device__ __forceinline__ void mma_f16(float* d,
    uint32_t a0, uint32_t a1, uint32_t a2, uint32_t a3,
    uint32_t b0, uint32_t b1) {
    asm volatile(
        "mma.sync.aligned.m16n8k16.row.col.f32.f16.f16.f32 "
        "{%0,%1,%2,%3},{%4,%5,%6,%7},{%8,%9},{%0,%1,%2,%3};"
        : "+f"(d[0]), "+f"(d[1]), "+f"(d[2]), "+f"(d[3])
        : "r"(a0), "r"(a1), "r"(a2), "r"(a3), "r"(b0), "r"(b1));
}

__device__ __forceinline__ uint32_t pack2(float a, float b) {
    __half2 h = __floats2half2_rn(a, b);
    return *(uint32_t*)&h;
}

__device__ __forceinline__ float warp_max(float v) {
    #pragma unroll
    for (int o = 16; o; o >>= 1) v = fmaxf(v, __shfl_xor_sync(0xFFFFFFFFu, v, o));
    return v;
}
__device__ __forceinline__ float warp_sum(float v) {
    #pragma unroll
    for (int o = 16; o; o >>= 1) v += __shfl_xor_sync(0xFFFFFFFFu, v, o);
    return v;
}

// half offset of element (r, k) inside blocked [R x K] matrix (Kd = K size).
__device__ __forceinline__ long blk_off(int r, int k, int Kd) {
    return ((long)(r >> 4) * (Kd >> 4) + (k >> 4)) * 256
         + ((r & 7) * 4 + ((k >> 1) & 3)) * 8
         + ((r >> 3) & 1) * 4 + ((k >> 3) & 1) * 2 + (k & 1);
}

// ---------------------------------------------------------------------------
// Pack fp32 row-major [R x Kd] -> fp16 blocked.  One thread produces TWO
// adjacent 16B chunks from 4 coalesced float4 loads.  nth = R*Kd/16.
// ---------------------------------------------------------------------------
__global__ void __launch_bounds__(256)
pack_rm(const float* __restrict__ in, __half* __restrict__ out,
        int Kd, long nth)
{
    long t = (long)blockIdx.x * blockDim.x + threadIdx.x;
    if (t >= nth) return;
    const long blk = t >> 4;
    const int sub = (int)(t & 15);
    const int g = sub >> 1, qh = sub & 1;
    const int Kb = Kd >> 4;
    const int rb = (int)(blk / Kb), kb = (int)(blk % Kb);
    const int r = rb * 16 + g;
    const float* p = in + (long)r * Kd + kb * 16 + qh * 4;
    float4 lo  = *(const float4*)p;
    float4 lo8 = *(const float4*)(p + 8);
    float4 hi  = *(const float4*)(p + (long)8 * Kd);
    float4 hi8 = *(const float4*)(p + (long)8 * Kd + 8);
    uint4 u0, u1;
    u0.x = pack2(lo.x, lo.y);   u0.y = pack2(lo8.x, lo8.y);
    u0.z = pack2(hi.x, hi.y);   u0.w = pack2(hi8.x, hi8.y);
    u1.x = pack2(lo.z, lo.w);   u1.y = pack2(lo8.z, lo8.w);
    u1.z = pack2(hi.z, hi.w);   u1.w = pack2(hi8.z, hi8.w);
    uint4* o = (uint4*)out + blk * 32 + g * 4 + 2 * qh;
    o[0] = u0;
    o[1] = u1;
}

// ---------------------------------------------------------------------------
// Transpose fp32 [Rin x Cin] -> fp16 blocked [Cin x Rin].  (weights only)
// ---------------------------------------------------------------------------
__global__ void __launch_bounds__(256)
pack_t(const float* __restrict__ in, __half* __restrict__ out, int Rin, int Cin)
{
    __shared__ float t[32][33];
    const int r0 = blockIdx.x * 32, c0 = blockIdx.y * 32;
    const int x = threadIdx.x, y = threadIdx.y;     // (32, 8)
    #pragma unroll
    for (int i = 0; i < 32; i += 8)
        t[y + i][x] = in[(long)(r0 + y + i) * Cin + c0 + x];
    __syncthreads();

    const int tid = y * 32 + x;
    if (tid < 128) {
        const int blk = tid >> 5, idx = tid & 31;
        const int brl = blk >> 1, bkl = blk & 1;
        const int g = idx >> 2, q = idx & 3;
        const int E  = 16 * brl + g;       // out-row within 32 (orig col)
        const int S0 = 16 * bkl + 2 * q;   // out-k within 32 (orig row)
        uint4 u;
        u.x = pack2(t[S0][E],         t[S0 + 1][E]);
        u.y = pack2(t[S0 + 8][E],     t[S0 + 9][E]);
        u.z = pack2(t[S0][E + 8],     t[S0 + 1][E + 8]);
        u.w = pack2(t[S0 + 8][E + 8], t[S0 + 9][E + 8]);
        const long chunk =
            ((long)((c0 >> 4) + brl) * (Rin >> 4) + (r0 >> 4) + bkl) * 32 + idx;
        ((uint4*)out)[chunk] = u;
    }
}

// ---------------------------------------------------------------------------
// FP16 mma.sync GEMM on blocked operands:  C[M,N] = A[M,K] * B[N,K]^T
// CTA 64(M) x 128(N), 8 warps (2x4), warp tile 32x32.
// K-chunk 32 per pipeline stage, 4 stages, ONE __syncthreads per chunk.
// __launch_bounds__(256, 3): 3 CTAs/SM.
// REVY: reverse blockIdx.y -> m0 so heaviest (large-m0) CTAs launch first.
// EPI: 0 = fp32 row-major (batched)
//      3 = fused QKV routing: n0<1024 -> g_Qh, <2048 -> g_Kh,
//          else -> g_Vt TRANSPOSED per batch (blocked fp16)
// ---------------------------------------------------------------------------
template <bool CAUSAL_SKIP, bool KLIMIT, bool REVY, int EPI>
__global__ void __launch_bounds__(256, 3)
hgemm(const __half* __restrict__ A, const __half* __restrict__ B, void* Cout,
      int Kd, int ldc, long sA, long sB, long sC)
{
    const int by = REVY ? (gridDim.y - 1 - blockIdx.y) : blockIdx.y;
    const int m0 = by * 64;
    const int n0 = blockIdx.x * 128;
    if (CAUSAL_SKIP && n0 > m0 + 63) return;

    A += (long)blockIdx.z * sA;
    B += (long)blockIdx.z * sB;

    const int Keff = KLIMIT ? min(Kd, m0 + 64) : Kd;
    const int nkt  = Keff >> 5;          // K-chunks of 32
    const int Kb   = Kd >> 4;            // 16-K blocks per row

    __shared__ uint4 sm[4][768];         // 48 KB

    const int tid  = threadIdx.x;
    const int warp = tid >> 5;
    const int lane = tid & 31;
    const int wm   = warp >> 2;          // 0..1
    const int wn   = warp & 3;           // 0..3

    // A loader: 256 chunks, 1/thread
    const int akb = tid >> 7;            // 0..1
    const int amb = (tid >> 5) & 3;      // 0..3
    const uint4* ag = (const uint4*)A + ((long)((m0 >> 4) + amb) * Kb + akb) * 32 + lane;
    const int asmi = akb * 128 + amb * 32 + lane;
    // B loader: 512 chunks, 2/thread (kb = i, nb = warp)
    const uint4* bg0 = (const uint4*)B + ((long)((n0 >> 4) + warp) * Kb + 0) * 32 + lane;
    const uint4* bg1 = (const uint4*)B + ((long)((n0 >> 4) + warp) * Kb + 1) * 32 + lane;
    const int bsmi0 = 256 +       warp * 32 + lane;
    const int bsmi1 = 256 + 256 + warp * 32 + lane;

    auto load_stage = [&](int st, int kt) {
        const long koff = (long)kt * 64;   // 2 blocks of 32 chunks
        cp16(&sm[st][asmi],  ag  + koff);
        cp16(&sm[st][bsmi0], bg0 + koff);
        cp16(&sm[st][bsmi1], bg1 + koff);
    };

    #pragma unroll
    for (int s = 0; s < 3; s++) {
        if (s < nkt) load_stage(s, s);
        asm volatile("cp.async.commit_group;\n");
    }

    float acc[2][4][4] = {};

    for (int kt = 0; kt < nkt; ++kt) {
        const int cur = kt & 3;
        asm volatile("cp.async.wait_group 2;\n");
        __syncthreads();   // data ready + all warps done reading slot (kt+3)&3

        if (kt + 3 < nkt) load_stage((kt + 3) & 3, kt + 3);
        asm volatile("cp.async.commit_group;\n");

        #pragma unroll
        for (int kb = 0; kb < 2; kb++) {
            uint4 Aq[2], Bq[2];
            #pragma unroll
            for (int mi = 0; mi < 2; mi++)
                Aq[mi] = sm[cur][kb * 128 + (wm * 2 + mi) * 32 + lane];
            #pragma unroll
            for (int nj = 0; nj < 2; nj++)
                Bq[nj] = sm[cur][256 + kb * 256 + (wn * 2 + nj) * 32 + lane];

            #pragma unroll
            for (int mi = 0; mi < 2; mi++) {
                mma_f16(acc[mi][0], Aq[mi].x, Aq[mi].z, Aq[mi].y, Aq[mi].w, Bq[0].x, Bq[0].y);
                mma_f16(acc[mi][1], Aq[mi].x, Aq[mi].z, Aq[mi].y, Aq[mi].w, Bq[0].z, Bq[0].w);
                mma_f16(acc[mi][2], Aq[mi].x, Aq[mi].z, Aq[mi].y, Aq[mi].w, Bq[1].x, Bq[1].y);
                mma_f16(acc[mi][3], Aq[mi].x, Aq[mi].z, Aq[mi].y, Aq[mi].w, Bq[1].z, Bq[1].w);
            }
        }
    }

    // Epilogue
    if (EPI == 3) {
        // fused QKV: route by output column group (uniform per CTA)
        const int w  = n0 >> 10;            // 0=Q, 1=K, 2=V
        const int nb = n0 & 1023;           // column base within the target
        #pragma unroll
        for (int mi = 0; mi < 2; mi++) {
            #pragma unroll
            for (int nt = 0; nt < 4; nt++) {
                const int r0 = m0 + wm * 32 + mi * 16 + (lane >> 2);
                const int c0 = nb + wn * 32 + nt * 8 + 2 * (lane & 3);
                if (w == 0) {
                    const long off = blk_off(r0, c0, Dm);
                    *(uint32_t*)(g_Qh + off)     = pack2(acc[mi][nt][0], acc[mi][nt][1]);
                    *(uint32_t*)(g_Qh + off + 4) = pack2(acc[mi][nt][2], acc[mi][nt][3]);
                } else if (w == 1) {
                    const long off = blk_off(r0, c0, Dm);
                    *(uint32_t*)(g_Kh + off)     = pack2(acc[mi][nt][0], acc[mi][nt][1]);
                    *(uint32_t*)(g_Kh + off + 4) = pack2(acc[mi][nt][2], acc[mi][nt][3]);
                } else {
                    const int b   = r0 >> 11;
                    const int rb0 = r0 & 2047;
                    __half* Vb = g_Vt + (long)b * Sq * Dm;
                    Vb[blk_off(c0,     rb0,     Sq)] = __float2half_rn(acc[mi][nt][0]);
                    Vb[blk_off(c0 + 1, rb0,     Sq)] = __float2half_rn(acc[mi][nt][1]);
                    Vb[blk_off(c0,     rb0 + 8, Sq)] = __float2half_rn(acc[mi][nt][2]);
                    Vb[blk_off(c0 + 1, rb0 + 8, Sq)] = __float2half_rn(acc[mi][nt][3]);
                }
            }
        }
    } else {
        float* Cf = (float*)Cout + (long)blockIdx.z * sC;
        #pragma unroll
        for (int mi = 0; mi < 2; mi++) {
            #pragma unroll
            for (int nt = 0; nt < 4; nt++) {
                const int r0 = m0 + wm * 32 + mi * 16 + (lane >> 2);
                const int c0 = n0 + wn * 32 + nt * 8 + 2 * (lane & 3);
                *(float2*)&Cf[(long)r0 * ldc + c0] =
                    make_float2(acc[mi][nt][0], acc[mi][nt][1]);
                *(float2*)&Cf[(long)(r0 + 8) * ldc + c0] =
                    make_float2(acc[mi][nt][2], acc[mi][nt][3]);
            }
        }
    }
}

// ---------------------------------------------------------------------------
// Causal row softmax: fp32 scores (row-major) -> fp16 probs (blocked).
// Logits s/32.  Zero-fills [len, ceil64(len)); PV reads exactly that far.
// ---------------------------------------------------------------------------
__global__ void __launch_bounds__(256)
softmax_k(const float* __restrict__ S, __half* __restrict__ Ph)
{
    const int row = blockIdx.x;
    const int b = row >> 11;
    const int i = row & 2047;
    const float* p = S + ((long)b * Sq + i) * Sq;
    __half* ph = Ph + (long)b * Sq * Sq;
    const int tid = threadIdx.x;
    const int len = i + 1;
    const int lenPad = (len + 63) & ~63;
    const int nquads = lenPad >> 2;

    float e[2][4];
    #pragma unroll
    for (int k = 0; k < 2; k++) {
        const int j4 = tid + 256 * k;
        if (j4 < nquads) {
            const float4 v = ((const float4*)p)[j4];
            const int j = 4 * j4;
            e[k][0] = (j     < len) ? v.x : -3.4e38f;
            e[k][1] = (j + 1 < len) ? v.y : -3.4e38f;
            e[k][2] = (j + 2 < len) ? v.z : -3.4e38f;
            e[k][3] = (j + 3 < len) ? v.w : -3.4e38f;
        } else {
            e[k][0] = e[k][1] = e[k][2] = e[k][3] = -3.4e38f;
        }
    }

    float mx = -3.4e38f;
    #pragma unroll
    for (int k = 0; k < 2; k++)
        #pragma unroll
        for (int u = 0; u < 4; u++) mx = fmaxf(mx, e[k][u]);
    mx = warp_max(mx);

    __shared__ float red[8];
    if ((tid & 31) == 0) red[tid >> 5] = mx;
    __syncthreads();
    mx = red[0];
    #pragma unroll
    for (int w = 1; w < 8; w++) mx = fmaxf(mx, red[w]);

    float s = 0.f;
    #pragma unroll
    for (int k = 0; k < 2; k++)
        #pragma unroll
        for (int u = 0; u < 4; u++) {
            e[k][u] = __expf((e[k][u] - mx) * 0.03125f);
            s += e[k][u];
        }
    s = warp_sum(s);
    __syncthreads();
    if ((tid & 31) == 0) red[tid >> 5] = s;
    __syncthreads();
    float tot = 0.f;
    #pragma unroll
    for (int w = 0; w < 8; w++) tot += red[w];
    const float inv = 1.0f / tot;

    #pragma unroll
    for (int k = 0; k < 2; k++) {
        const int j4 = tid + 256 * k;
        if (j4 < nquads) {
            const int j = 4 * j4;
            *(uint32_t*)(ph + blk_off(i, j, Sq)) =
                pack2(e[k][0] * inv, e[k][1] * inv);
            *(uint32_t*)(ph + blk_off(i, j + 2, Sq)) =
                pack2(e[k][2] * inv, e[k][3] * inv);
        }
    }
}

// ---------------------------------------------------------------------------
extern "C" void kernel_launch(void* const* d_in, const int* in_sizes, int n_in,
                              void* d_out, int out_size)
{
    const float* x  = (const float*)d_in[0];
    const float* Wq = (const float*)d_in[1];
    const float* Wk = (const float*)d_in[2];
    const float* Wv = (const float*)d_in[3];
    float* out = (float*)d_out;

    __half *Xh, *Wcat, *Qh, *Kh, *Vt, *Ph;
    float *Sb;
    cudaGetSymbolAddress((void**)&Xh,   g_Xh);
    cudaGetSymbolAddress((void**)&Wcat, g_Wcat);
    cudaGetSymbolAddress((void**)&Qh,   g_Qh);
    cudaGetSymbolAddress((void**)&Kh,   g_Kh);
    cudaGetSymbolAddress((void**)&Vt,   g_Vt);
    cudaGetSymbolAddress((void**)&Sb,   g_S);
    cudaGetSymbolAddress((void**)&Ph,   g_Ph);

    // Max shared-memory carveout so 3 CTAs x 48KB fit per SM
    cudaFuncSetAttribute((const void*)hgemm<false, false, false, 3>,
        cudaFuncAttributePreferredSharedMemoryCarveout, 100);
    cudaFuncSetAttribute((const void*)hgemm<true, false, true, 0>,
        cudaFuncAttributePreferredSharedMemoryCarveout, 100);
    cudaFuncSetAttribute((const void*)hgemm<false, true, true, 0>,
        cudaFuncAttributePreferredSharedMemoryCarveout, 100);

    const int M = Bsz * Sq;   // 8192

    // 0) pack x; pack all three W^T into one concatenated blocked buffer
    {
        const long nth = (long)M * Dm / 16;
        pack_rm<<<(int)((nth + 255) / 256), 256>>>(x, Xh, Dm, nth);
        dim3 tb(32, 8);
        dim3 gw(Dm / 32, Dm / 32, 1);
        pack_t<<<gw, tb>>>(Wq, Wcat,                     Dm, Dm);
        pack_t<<<gw, tb>>>(Wk, Wcat + (long)Dm * Dm,     Dm, Dm);
        pack_t<<<gw, tb>>>(Wv, Wcat + (long)2 * Dm * Dm, Dm, Dm);
    }

    // 1) Fused QKV projection: one launch, epilogue routes Q/K/Vt
    {
        dim3 grid((3 * Dm) / 128, M / 64, 1);
        hgemm<false, false, false, 3><<<grid, 256>>>(
            Xh, Wcat, nullptr, Dm, Dm, 0, 0, 0);
    }

    // 2) Scores: S_b = Q_b K_b^T (causal-skip, heavy rows first)
    {
        dim3 grid(Sq / 128, Sq / 64, Bsz);
        hgemm<true, false, true, 0><<<grid, 256>>>(
            Qh, Kh, Sb, Dm, Sq,
            (long)Sq * Dm, (long)Sq * Dm, (long)Sq * Sq);
    }

    // 3) Softmax -> fp16 blocked probs
    softmax_k<<<Bsz * Sq, 256>>>(Sb, Ph);

    // 4) O = P Vt^T (causal K-limit, heavy rows first), fp32 out
    {
        dim3 grid(Dm / 128, Sq / 64, Bsz);
        hgemm<false, true, true, 0><<<grid, 256>>>(
            Ph, Vt, out, Sq, Dm,
            (long)Sq * Sq, (long)Sq * Dm, (long)Sq * Dm);
    }

    (void)in_sizes; (void)n_in; (void)out_size;
}

// round 13
// speedup vs baseline: 1.3668x; 1.0010x over previous
#include <cuda_runtime.h>
#include <cuda_fp16.h>
#include <cstdint>

// Problem constants
constexpr int Bsz = 4;
constexpr int Sq  = 2048;
constexpr int Dm  = 1024;

// Scratch (device globals; no allocation allowed).
// "blocked" fp16 layout: matrix [R x K] split into 16x16 blocks, block
// (br,bk) stored at (br*(K/16)+bk)*256 halves; inside a block, 16B chunk
// (g,q), g=0..7,q=0..3 (chunk idx = g*4+q), holds halves
//   x: [row g,   k 2q,2q+1]   y: [row g,   k 2q+8,2q+9]
//   z: [row g+8, k 2q,2q+1]   w: [row g+8, k 2q+8,2q+9]
// One LDS.128 = one full m16n8k16 A-fragment (regs x,z,y,w) or two
// B-fragments (n=g via x,y and n=g+8 via z,w).
__device__ __half g_Xh  [(long)Bsz * Sq * Dm];
__device__ __half g_Wcat[(long)3 * Dm * Dm];    // WqT | WkT | WvT (row-concat)
__device__ __half g_Qh  [(long)Bsz * Sq * Dm];
__device__ __half g_Kh  [(long)Bsz * Sq * Dm];
__device__ __half g_Vt  [(long)Bsz * Sq * Dm];  // V^T per batch, blocked
__device__ __half g_Sh  [(long)Bsz * Sq * Sq];  // fp16 scores, row-major
__device__ __half g_Ph  [(long)Bsz * Sq * Sq];  // fp16 probs, blocked

// ---------------------------------------------------------------------------
// helpers
// ---------------------------------------------------------------------------
__device__ __forceinline__ void cp16(void* s, const void* g) {
    uint32_t sa = (uint32_t)__cvta_generic_to_shared(s);
    asm volatile("cp.async.cg.shared.global [%0], [%1], 16;\n" :: "r"(sa), "l"(g));
}

__device__ __forceinline__ void mma_f16(float* d,
    uint32_t a0, uint32_t a1, uint32_t a2, uint32_t a3,
    uint32_t b0, uint32_t b1) {
    asm volatile(
        "mma.sync.aligned.m16n8k16.row.col.f32.f16.f16.f32 "
        "{%0,%1,%2,%3},{%4,%5,%6,%7},{%8,%9},{%0,%1,%2,%3};"
        : "+f"(d[0]), "+f"(d[1]), "+f"(d[2]), "+f"(d[3])
        : "r"(a0), "r"(a1), "r"(a2), "r"(a3), "r"(b0), "r"(b1));
}

__device__ __forceinline__ uint32_t pack2(float a, float b) {
    __half2 h = __floats2half2_rn(a, b);
    return *(uint32_t*)&h;
}

__device__ __forceinline__ float warp_max(float v) {
    #pragma unroll
    for (int o = 16; o; o >>= 1) v = fmaxf(v, __shfl_xor_sync(0xFFFFFFFFu, v, o));
    return v;
}
__device__ __forceinline__ float warp_sum(float v) {
    #pragma unroll
    for (int o = 16; o; o >>= 1) v += __shfl_xor_sync(0xFFFFFFFFu, v, o);
    return v;
}

// half offset of element (r, k) inside blocked [R x K] matrix (Kd = K size).
__device__ __forceinline__ long blk_off(int r, int k, int Kd) {
    return ((long)(r >> 4) * (Kd >> 4) + (k >> 4)) * 256
         + ((r & 7) * 4 + ((k >> 1) & 3)) * 8
         + ((r >> 3) & 1) * 4 + ((k >> 3) & 1) * 2 + (k & 1);
}

// ---------------------------------------------------------------------------
// Pack fp32 row-major [R x Kd] -> fp16 blocked.  One thread produces TWO
// adjacent 16B chunks from 4 coalesced float4 loads.  nth = R*Kd/16.
// ---------------------------------------------------------------------------
__global__ void __launch_bounds__(256)
pack_rm(const float* __restrict__ in, __half* __restrict__ out,
        int Kd, long nth)
{
    long t = (long)blockIdx.x * blockDim.x + threadIdx.x;
    if (t >= nth) return;
    const long blk = t >> 4;
    const int sub = (int)(t & 15);
    const int g = sub >> 1, qh = sub & 1;
    const int Kb = Kd >> 4;
    const int rb = (int)(blk / Kb), kb = (int)(blk % Kb);
    const int r = rb * 16 + g;
    const float* p = in + (long)r * Kd + kb * 16 + qh * 4;
    float4 lo  = *(const float4*)p;
    float4 lo8 = *(const float4*)(p + 8);
    float4 hi  = *(const float4*)(p + (long)8 * Kd);
    float4 hi8 = *(const float4*)(p + (long)8 * Kd + 8);
    uint4 u0, u1;
    u0.x = pack2(lo.x, lo.y);   u0.y = pack2(lo8.x, lo8.y);
    u0.z = pack2(hi.x, hi.y);   u0.w = pack2(hi8.x, hi8.y);
    u1.x = pack2(lo.z, lo.w);   u1.y = pack2(lo8.z, lo8.w);
    u1.z = pack2(hi.z, hi.w);   u1.w = pack2(hi8.z, hi8.w);
    uint4* o = (uint4*)out + blk * 32 + g * 4 + 2 * qh;
    o[0] = u0;
    o[1] = u1;
}

// ---------------------------------------------------------------------------
// Transpose 3 fp32 [Dm x Dm] weights -> fp16 blocked [Dm x Dm] each, into
// one concatenated buffer.  blockIdx.z selects the source.
// ---------------------------------------------------------------------------
__global__ void __launch_bounds__(256)
pack_t3(const float* __restrict__ w0, const float* __restrict__ w1,
        const float* __restrict__ w2, __half* __restrict__ out)
{
    __shared__ float t[32][33];
    const float* in = (blockIdx.z == 0) ? w0 : (blockIdx.z == 1) ? w1 : w2;
    __half* o = out + (long)blockIdx.z * Dm * Dm;
    const int r0 = blockIdx.x * 32, c0 = blockIdx.y * 32;
    const int x = threadIdx.x, y = threadIdx.y;     // (32, 8)
    #pragma unroll
    for (int i = 0; i < 32; i += 8)
        t[y + i][x] = in[(long)(r0 + y + i) * Dm + c0 + x];
    __syncthreads();

    const int tid = y * 32 + x;
    if (tid < 128) {
        const int blk = tid >> 5, idx = tid & 31;
        const int brl = blk >> 1, bkl = blk & 1;
        const int g = idx >> 2, q = idx & 3;
        const int E  = 16 * brl + g;       // out-row within 32 (orig col)
        const int S0 = 16 * bkl + 2 * q;   // out-k within 32 (orig row)
        uint4 u;
        u.x = pack2(t[S0][E],         t[S0 + 1][E]);
        u.y = pack2(t[S0 + 8][E],     t[S0 + 9][E]);
        u.z = pack2(t[S0][E + 8],     t[S0 + 1][E + 8]);
        u.w = pack2(t[S0 + 8][E + 8], t[S0 + 9][E + 8]);
        const long chunk =
            ((long)((c0 >> 4) + brl) * (Dm >> 4) + (r0 >> 4) + bkl) * 32 + idx;
        ((uint4*)o)[chunk] = u;
    }
}

// ---------------------------------------------------------------------------
// FP16 mma.sync GEMM on blocked operands:  C[M,N] = A[M,K] * B[N,K]^T
// CTA 64(M) x 128(N), 8 warps (2x4), warp tile 32x32.
// K-chunk 32 per pipeline stage, 4 stages, ONE __syncthreads per chunk.
// __launch_bounds__(256, 3): 3 CTAs/SM.
// REVY: reverse blockIdx.y -> m0 so heaviest (large-m0) CTAs launch first.
// EPI: 0 = fp32 row-major (batched)
//      3 = fused QKV routing: n0<1024 -> g_Qh, <2048 -> g_Kh,
//          else -> g_Vt TRANSPOSED per batch (blocked fp16)
//      4 = fp16 row-major (batched)  [scores]
// ---------------------------------------------------------------------------
template <bool CAUSAL_SKIP, bool KLIMIT, bool REVY, int EPI>
__global__ void __launch_bounds__(256, 3)
hgemm(const __half* __restrict__ A, const __half* __restrict__ B, void* Cout,
      int Kd, int ldc, long sA, long sB, long sC)
{
    const int by = REVY ? (gridDim.y - 1 - blockIdx.y) : blockIdx.y;
    const int m0 = by * 64;
    const int n0 = blockIdx.x * 128;
    if (CAUSAL_SKIP && n0 > m0 + 63) return;

    A += (long)blockIdx.z * sA;
    B += (long)blockIdx.z * sB;

    const int Keff = KLIMIT ? min(Kd, m0 + 64) : Kd;
    const int nkt  = Keff >> 5;          // K-chunks of 32
    const int Kb   = Kd >> 4;            // 16-K blocks per row

    __shared__ uint4 sm[4][768];         // 48 KB

    const int tid  = threadIdx.x;
    const int warp = tid >> 5;
    const int lane = tid & 31;
    const int wm   = warp >> 2;          // 0..1
    const int wn   = warp & 3;           // 0..3

    // A loader: 256 chunks, 1/thread
    const int akb = tid >> 7;            // 0..1
    const int amb = (tid >> 5) & 3;      // 0..3
    const uint4* ag = (const uint4*)A + ((long)((m0 >> 4) + amb) * Kb + akb) * 32 + lane;
    const int asmi = akb * 128 + amb * 32 + lane;
    // B loader: 512 chunks, 2/thread (kb = i, nb = warp)
    const uint4* bg0 = (const uint4*)B + ((long)((n0 >> 4) + warp) * Kb + 0) * 32 + lane;
    const uint4* bg1 = (const uint4*)B + ((long)((n0 >> 4) + warp) * Kb + 1) * 32 + lane;
    const int bsmi0 = 256 +       warp * 32 + lane;
    const int bsmi1 = 256 + 256 + warp * 32 + lane;

    auto load_stage = [&](int st, int kt) {
        const long koff = (long)kt * 64;   // 2 blocks of 32 chunks
        cp16(&sm[st][asmi],  ag  + koff);
        cp16(&sm[st][bsmi0], bg0 + koff);
        cp16(&sm[st][bsmi1], bg1 + koff);
    };

    #pragma unroll
    for (int s = 0; s < 3; s++) {
        if (s < nkt) load_stage(s, s);
        asm volatile("cp.async.commit_group;\n");
    }

    float acc[2][4][4] = {};

    for (int kt = 0; kt < nkt; ++kt) {
        const int cur = kt & 3;
        asm volatile("cp.async.wait_group 2;\n");
        __syncthreads();   // data ready + all warps done reading slot (kt+3)&3

        if (kt + 3 < nkt) load_stage((kt + 3) & 3, kt + 3);
        asm volatile("cp.async.commit_group;\n");

        #pragma unroll
        for (int kb = 0; kb < 2; kb++) {
            uint4 Aq[2], Bq[2];
            #pragma unroll
            for (int mi = 0; mi < 2; mi++)
                Aq[mi] = sm[cur][kb * 128 + (wm * 2 + mi) * 32 + lane];
            #pragma unroll
            for (int nj = 0; nj < 2; nj++)
                Bq[nj] = sm[cur][256 + kb * 256 + (wn * 2 + nj) * 32 + lane];

            #pragma unroll
            for (int mi = 0; mi < 2; mi++) {
                mma_f16(acc[mi][0], Aq[mi].x, Aq[mi].z, Aq[mi].y, Aq[mi].w, Bq[0].x, Bq[0].y);
                mma_f16(acc[mi][1], Aq[mi].x, Aq[mi].z, Aq[mi].y, Aq[mi].w, Bq[0].z, Bq[0].w);
                mma_f16(acc[mi][2], Aq[mi].x, Aq[mi].z, Aq[mi].y, Aq[mi].w, Bq[1].x, Bq[1].y);
                mma_f16(acc[mi][3], Aq[mi].x, Aq[mi].z, Aq[mi].y, Aq[mi].w, Bq[1].z, Bq[1].w);
            }
        }
    }

    // Epilogue
    if (EPI == 3) {
        // fused QKV: route by output column group (uniform per CTA)
        const int w  = n0 >> 10;            // 0=Q, 1=K, 2=V
        const int nb = n0 & 1023;           // column base within the target
        #pragma unroll
        for (int mi = 0; mi < 2; mi++) {
            #pragma unroll
            for (int nt = 0; nt < 4; nt++) {
                const int r0 = m0 + wm * 32 + mi * 16 + (lane >> 2);
                const int c0 = nb + wn * 32 + nt * 8 + 2 * (lane & 3);
                if (w == 0) {
                    const long off = blk_off(r0, c0, Dm);
                    *(uint32_t*)(g_Qh + off)     = pack2(acc[mi][nt][0], acc[mi][nt][1]);
                    *(uint32_t*)(g_Qh + off + 4) = pack2(acc[mi][nt][2], acc[mi][nt][3]);
                } else if (w == 1) {
                    const long off = blk_off(r0, c0, Dm);
                    *(uint32_t*)(g_Kh + off)     = pack2(acc[mi][nt][0], acc[mi][nt][1]);
                    *(uint32_t*)(g_Kh + off + 4) = pack2(acc[mi][nt][2], acc[mi][nt][3]);
                } else {
                    const int b   = r0 >> 11;
                    const int rb0 = r0 & 2047;
                    __half* Vb = g_Vt + (long)b * Sq * Dm;
                    Vb[blk_off(c0,     rb0,     Sq)] = __float2half_rn(acc[mi][nt][0]);
                    Vb[blk_off(c0 + 1, rb0,     Sq)] = __float2half_rn(acc[mi][nt][1]);
                    Vb[blk_off(c0,     rb0 + 8, Sq)] = __float2half_rn(acc[mi][nt][2]);
                    Vb[blk_off(c0 + 1, rb0 + 8, Sq)] = __float2half_rn(acc[mi][nt][3]);
                }
            }
        }
    } else if (EPI == 4) {
        __half* Cf = (__half*)Cout + (long)blockIdx.z * sC;
        #pragma unroll
        for (int mi = 0; mi < 2; mi++) {
            #pragma unroll
            for (int nt = 0; nt < 4; nt++) {
                const int r0 = m0 + wm * 32 + mi * 16 + (lane >> 2);
                const int c0 = n0 + wn * 32 + nt * 8 + 2 * (lane & 3);
                *(uint32_t*)&Cf[(long)r0 * ldc + c0] =
                    pack2(acc[mi][nt][0], acc[mi][nt][1]);
                *(uint32_t*)&Cf[(long)(r0 + 8) * ldc + c0] =
                    pack2(acc[mi][nt][2], acc[mi][nt][3]);
            }
        }
    } else {
        float* Cf = (float*)Cout + (long)blockIdx.z * sC;
        #pragma unroll
        for (int mi = 0; mi < 2; mi++) {
            #pragma unroll
            for (int nt = 0; nt < 4; nt++) {
                const int r0 = m0 + wm * 32 + mi * 16 + (lane >> 2);
                const int c0 = n0 + wn * 32 + nt * 8 + 2 * (lane & 3);
                *(float2*)&Cf[(long)r0 * ldc + c0] =
                    make_float2(acc[mi][nt][0], acc[mi][nt][1]);
                *(float2*)&Cf[(long)(r0 + 8) * ldc + c0] =
                    make_float2(acc[mi][nt][2], acc[mi][nt][3]);
            }
        }
    }
}

// ---------------------------------------------------------------------------
// Causal row softmax: fp16 scores (row-major) -> fp16 probs (blocked).
// Logits s/32.  Zero-fills [len, ceil64(len)); PV reads exactly that far.
// Each thread loads one 16B oct (8 halves); 2048/8 = 256 = blockDim.
// ---------------------------------------------------------------------------
__global__ void __launch_bounds__(256)
softmax_k(const __half* __restrict__ S, __half* __restrict__ Ph)
{
    const int row = blockIdx.x;
    const int b = row >> 11;
    const int i = row & 2047;
    const __half* p = S + ((long)b * Sq + i) * Sq;
    __half* ph = Ph + (long)b * Sq * Sq;
    const int tid = threadIdx.x;
    const int len = i + 1;
    const int lenPad = (len + 63) & ~63;
    const int noct = lenPad >> 3;

    float e[8];
    const int j0 = tid * 8;
    if (tid < noct) {
        uint4 u = ((const uint4*)p)[tid];
        const __half* h = (const __half*)&u;
        #pragma unroll
        for (int s = 0; s < 8; s++)
            e[s] = (j0 + s < len) ? __half2float(h[s]) : -3.4e38f;
    } else {
        #pragma unroll
        for (int s = 0; s < 8; s++) e[s] = -3.4e38f;
    }

    float mx = -3.4e38f;
    #pragma unroll
    for (int s = 0; s < 8; s++) mx = fmaxf(mx, e[s]);
    mx = warp_max(mx);

    __shared__ float red[8];
    if ((tid & 31) == 0) red[tid >> 5] = mx;
    __syncthreads();
    mx = red[0];
    #pragma unroll
    for (int w = 1; w < 8; w++) mx = fmaxf(mx, red[w]);

    float sum = 0.f;
    #pragma unroll
    for (int s = 0; s < 8; s++) {
        e[s] = __expf((e[s] - mx) * 0.03125f);
        sum += e[s];
    }
    sum = warp_sum(sum);
    __syncthreads();
    if ((tid & 31) == 0) red[tid >> 5] = sum;
    __syncthreads();
    float tot = 0.f;
    #pragma unroll
    for (int w = 0; w < 8; w++) tot += red[w];
    const float inv = 1.0f / tot;

    if (tid < noct) {
        #pragma unroll
        for (int s = 0; s < 8; s += 2)
            *(uint32_t*)(ph + blk_off(i, j0 + s, Sq)) =
                pack2(e[s] * inv, e[s + 1] * inv);
    }
}

// ---------------------------------------------------------------------------
extern "C" void kernel_launch(void* const* d_in, const int* in_sizes, int n_in,
                              void* d_out, int out_size)
{
    const float* x  = (const float*)d_in[0];
    const float* Wq = (const float*)d_in[1];
    const float* Wk = (const float*)d_in[2];
    const float* Wv = (const float*)d_in[3];
    float* out = (float*)d_out;

    __half *Xh, *Wcat, *Qh, *Kh, *Vt, *Sh, *Ph;
    cudaGetSymbolAddress((void**)&Xh,   g_Xh);
    cudaGetSymbolAddress((void**)&Wcat, g_Wcat);
    cudaGetSymbolAddress((void**)&Qh,   g_Qh);
    cudaGetSymbolAddress((void**)&Kh,   g_Kh);
    cudaGetSymbolAddress((void**)&Vt,   g_Vt);
    cudaGetSymbolAddress((void**)&Sh,   g_Sh);
    cudaGetSymbolAddress((void**)&Ph,   g_Ph);

    // Max shared-memory carveout so 3 CTAs x 48KB fit per SM
    cudaFuncSetAttribute((const void*)hgemm<false, false, false, 3>,
        cudaFuncAttributePreferredSharedMemoryCarveout, 100);
    cudaFuncSetAttribute((const void*)hgemm<true, false, true, 4>,
        cudaFuncAttributePreferredSharedMemoryCarveout, 100);
    cudaFuncSetAttribute((const void*)hgemm<false, true, true, 0>,
        cudaFuncAttributePreferredSharedMemoryCarveout, 100);

    const int M = Bsz * Sq;   // 8192

    // 0) pack x; pack all three W^T in ONE launch
    {
        const long nth = (long)M * Dm / 16;
        pack_rm<<<(int)((nth + 255) / 256), 256>>>(x, Xh, Dm, nth);
        dim3 tb(32, 8);
        dim3 gw(Dm / 32, Dm / 32, 3);
        pack_t3<<<gw, tb>>>(Wq, Wk, Wv, Wcat);
    }

    // 1) Fused QKV projection: one launch, epilogue routes Q/K/Vt
    {
        dim3 grid((3 * Dm) / 128, M / 64, 1);
        hgemm<false, false, false, 3><<<grid, 256>>>(
            Xh, Wcat, nullptr, Dm, Dm, 0, 0, 0);
    }

    // 2) Scores: S_b = Q_b K_b^T (causal-skip, heavy rows first), fp16 out
    {
        dim3 grid(Sq / 128, Sq / 64, Bsz);
        hgemm<true, false, true, 4><<<grid, 256>>>(
            Qh, Kh, Sh, Dm, Sq,
            (long)Sq * Dm, (long)Sq * Dm, (long)Sq * Sq);
    }

    // 3) Softmax -> fp16 blocked probs
    softmax_k<<<Bsz * Sq, 256>>>(Sh, Ph);

    // 4) O = P Vt^T (causal K-limit, heavy rows first), fp32 out
    {
        dim3 grid(Dm / 128, Sq / 64, Bsz);
        hgemm<false, true, true, 0><<<grid, 256>>>(
            Ph, Vt, out, Sq, Dm,
            (long)Sq * Sq, (long)Sq * Dm, (long)Sq * Dm);
    }

    (void)in_sizes; (void)n_in; (void)out_size;
}

// round 14
// speedup vs baseline: 1.4134x; 1.0341x over previous
#include <cuda_runtime.h>
#include <cuda_fp16.h>
#include <cstdint>

// Problem constants
constexpr int Bsz = 4;
constexpr int Sq  = 2048;
constexpr int Dm  = 1024;

// Scratch (device globals; no allocation allowed).
// "blocked" fp16 layout: matrix [R x K] split into 16x16 blocks, block
// (br,bk) stored at (br*(K/16)+bk)*256 halves; inside a block, 16B chunk
// (g,q), g=0..7,q=0..3 (chunk idx = g*4+q), holds halves
//   x: [row g,   k 2q,2q+1]   y: [row g,   k 2q+8,2q+9]
//   z: [row g+8, k 2q,2q+1]   w: [row g+8, k 2q+8,2q+9]
// One LDS.128 = one full m16n8k16 A-fragment (regs x,z,y,w) or two
// B-fragments (n=g via x,y and n=g+8 via z,w).
__device__ __half g_Xh  [(long)Bsz * Sq * Dm];
__device__ __half g_Wcat[(long)3 * Dm * Dm];    // WqT | WkT | WvT (row-concat)
__device__ __half g_Qh  [(long)Bsz * Sq * Dm];
__device__ __half g_Kh  [(long)Bsz * Sq * Dm];
__device__ __half g_Vt  [(long)Bsz * Sq * Dm];  // V^T per batch, blocked
__device__ __half g_Sh  [(long)Bsz * Sq * Sq];  // fp16 scores, row-major
__device__ __half g_Ph  [(long)Bsz * Sq * Sq];  // fp16 probs, blocked

// ---------------------------------------------------------------------------
// helpers
// ---------------------------------------------------------------------------
__device__ __forceinline__ void cp16(void* s, const void* g) {
    uint32_t sa = (uint32_t)__cvta_generic_to_shared(s);
    asm volatile("cp.async.cg.shared.global [%0], [%1], 16;\n" :: "r"(sa), "l"(g));
}

__device__ __forceinline__ void mma_f16(float* d,
    uint32_t a0, uint32_t a1, uint32_t a2, uint32_t a3,
    uint32_t b0, uint32_t b1) {
    asm volatile(
        "mma.sync.aligned.m16n8k16.row.col.f32.f16.f16.f32 "
        "{%0,%1,%2,%3},{%4,%5,%6,%7},{%8,%9},{%0,%1,%2,%3};"
        : "+f"(d[0]), "+f"(d[1]), "+f"(d[2]), "+f"(d[3])
        : "r"(a0), "r"(a1), "r"(a2), "r"(a3), "r"(b0), "r"(b1));
}

__device__ __forceinline__ uint32_t pack2(float a, float b) {
    __half2 h = __floats2half2_rn(a, b);
    return *(uint32_t*)&h;
}

__device__ __forceinline__ float warp_max(float v) {
    #pragma unroll
    for (int o = 16; o; o >>= 1) v = fmaxf(v, __shfl_xor_sync(0xFFFFFFFFu, v, o));
    return v;
}
__device__ __forceinline__ float warp_sum(float v) {
    #pragma unroll
    for (int o = 16; o; o >>= 1) v += __shfl_xor_sync(0xFFFFFFFFu, v, o);
    return v;
}

// half offset of element (r, k) inside blocked [R x K] matrix (Kd = K size).
__device__ __forceinline__ long blk_off(int r, int k, int Kd) {
    return ((long)(r >> 4) * (Kd >> 4) + (k >> 4)) * 256
         + ((r & 7) * 4 + ((k >> 1) & 3)) * 8
         + ((r >> 3) & 1) * 4 + ((k >> 3) & 1) * 2 + (k & 1);
}

// ---------------------------------------------------------------------------
// Pack fp32 row-major [R x Kd] -> fp16 blocked.  One thread produces TWO
// adjacent 16B chunks from 4 coalesced float4 loads.  nth = R*Kd/16.
// ---------------------------------------------------------------------------
__global__ void __launch_bounds__(256)
pack_rm(const float* __restrict__ in, __half* __restrict__ out,
        int Kd, long nth)
{
    long t = (long)blockIdx.x * blockDim.x + threadIdx.x;
    if (t >= nth) return;
    const long blk = t >> 4;
    const int sub = (int)(t & 15);
    const int g = sub >> 1, qh = sub & 1;
    const int Kb = Kd >> 4;
    const int rb = (int)(blk / Kb), kb = (int)(blk % Kb);
    const int r = rb * 16 + g;
    const float* p = in + (long)r * Kd + kb * 16 + qh * 4;
    float4 lo  = *(const float4*)p;
    float4 lo8 = *(const float4*)(p + 8);
    float4 hi  = *(const float4*)(p + (long)8 * Kd);
    float4 hi8 = *(const float4*)(p + (long)8 * Kd + 8);
    uint4 u0, u1;
    u0.x = pack2(lo.x, lo.y);   u0.y = pack2(lo8.x, lo8.y);
    u0.z = pack2(hi.x, hi.y);   u0.w = pack2(hi8.x, hi8.y);
    u1.x = pack2(lo.z, lo.w);   u1.y = pack2(lo8.z, lo8.w);
    u1.z = pack2(hi.z, hi.w);   u1.w = pack2(hi8.z, hi8.w);
    uint4* o = (uint4*)out + blk * 32 + g * 4 + 2 * qh;
    o[0] = u0;
    o[1] = u1;
}

// ---------------------------------------------------------------------------
// Transpose 3 fp32 [Dm x Dm] weights -> fp16 blocked [Dm x Dm] each, into
// one concatenated buffer.  blockIdx.z selects the source.
// ---------------------------------------------------------------------------
__global__ void __launch_bounds__(256)
pack_t3(const float* __restrict__ w0, const float* __restrict__ w1,
        const float* __restrict__ w2, __half* __restrict__ out)
{
    __shared__ float t[32][33];
    const float* in = (blockIdx.z == 0) ? w0 : (blockIdx.z == 1) ? w1 : w2;
    __half* o = out + (long)blockIdx.z * Dm * Dm;
    const int r0 = blockIdx.x * 32, c0 = blockIdx.y * 32;
    const int x = threadIdx.x, y = threadIdx.y;     // (32, 8)
    #pragma unroll
    for (int i = 0; i < 32; i += 8)
        t[y + i][x] = in[(long)(r0 + y + i) * Dm + c0 + x];
    __syncthreads();

    const int tid = y * 32 + x;
    if (tid < 128) {
        const int blk = tid >> 5, idx = tid & 31;
        const int brl = blk >> 1, bkl = blk & 1;
        const int g = idx >> 2, q = idx & 3;
        const int E  = 16 * brl + g;       // out-row within 32 (orig col)
        const int S0 = 16 * bkl + 2 * q;   // out-k within 32 (orig row)
        uint4 u;
        u.x = pack2(t[S0][E],         t[S0 + 1][E]);
        u.y = pack2(t[S0 + 8][E],     t[S0 + 9][E]);
        u.z = pack2(t[S0][E + 8],     t[S0 + 1][E + 8]);
        u.w = pack2(t[S0 + 8][E + 8], t[S0 + 9][E + 8]);
        const long chunk =
            ((long)((c0 >> 4) + brl) * (Dm >> 4) + (r0 >> 4) + bkl) * 32 + idx;
        ((uint4*)o)[chunk] = u;
    }
}

// ---------------------------------------------------------------------------
// FP16 mma.sync GEMM on blocked operands:  C[M,N] = A[M,K] * B[N,K]^T
// CTA 64(M) x 128(N), 4 warps (2x2), warp tile 32x64.
// Per warp per K16: 2 A-LDS + 4 B-LDS = 6 LDS.128 per 16 HMMA (0.375
// ratio, 25% less smem-read than 8-warp/32x32).  K-chunk 32 per stage,
// 4 stages, ONE __syncthreads per chunk.  __launch_bounds__(128, 4).
// REVY: reverse blockIdx.y -> m0 so heaviest CTAs launch first.
// EPI: 0 = fp32 row-major (batched)
//      3 = fused QKV routing: n0<1024 -> g_Qh, <2048 -> g_Kh,
//          else -> g_Vt TRANSPOSED per batch (blocked fp16)
//      4 = fp16 row-major (batched)  [scores]
// ---------------------------------------------------------------------------
template <bool CAUSAL_SKIP, bool KLIMIT, bool REVY, int EPI>
__global__ void __launch_bounds__(128, 4)
hgemm(const __half* __restrict__ A, const __half* __restrict__ B, void* Cout,
      int Kd, int ldc, long sA, long sB, long sC)
{
    const int by = REVY ? (gridDim.y - 1 - blockIdx.y) : blockIdx.y;
    const int m0 = by * 64;
    const int n0 = blockIdx.x * 128;
    if (CAUSAL_SKIP && n0 > m0 + 63) return;

    A += (long)blockIdx.z * sA;
    B += (long)blockIdx.z * sB;

    const int Keff = KLIMIT ? min(Kd, m0 + 64) : Kd;
    const int nkt  = Keff >> 5;          // K-chunks of 32
    const int Kb   = Kd >> 4;            // 16-K blocks per row

    // per stage: A [0,256) = kb*128 + mb*32 + lane ; B [256,768) = 256 + kb*256 + nb*32 + lane
    __shared__ uint4 sm[4][768];         // 48 KB

    const int tid  = threadIdx.x;
    const int warp = tid >> 5;           // 0..3
    const int lane = tid & 31;
    const int wm   = warp >> 1;          // 0..1 (32 M-rows)
    const int wn   = warp & 1;           // 0..1 (64 N-cols)

    // A loader: 256 chunks per stage, 2/thread
    const uint4* agp[2];  int asmi[2];
    #pragma unroll
    for (int i = 0; i < 2; i++) {
        const int c  = tid + i * 128;
        const int kb = c >> 7, mb = (c >> 5) & 3, ln = c & 31;
        agp[i]  = (const uint4*)A + ((long)((m0 >> 4) + mb) * Kb + kb) * 32 + ln;
        asmi[i] = kb * 128 + mb * 32 + ln;
    }
    // B loader: 512 chunks per stage, 4/thread
    const uint4* bgp[4];  int bsmi[4];
    #pragma unroll
    for (int i = 0; i < 4; i++) {
        const int c  = tid + i * 128;
        const int kb = c >> 8, nb = (c >> 5) & 7, ln = c & 31;
        bgp[i]  = (const uint4*)B + ((long)((n0 >> 4) + nb) * Kb + kb) * 32 + ln;
        bsmi[i] = 256 + kb * 256 + nb * 32 + ln;
    }

    auto load_stage = [&](int st, int kt) {
        const long koff = (long)kt * 64;   // 2 blocks of 32 chunks per K32
        #pragma unroll
        for (int i = 0; i < 2; i++) cp16(&sm[st][asmi[i]], agp[i] + koff);
        #pragma unroll
        for (int i = 0; i < 4; i++) cp16(&sm[st][bsmi[i]], bgp[i] + koff);
    };

    #pragma unroll
    for (int s = 0; s < 3; s++) {
        if (s < nkt) load_stage(s, s);
        asm volatile("cp.async.commit_group;\n");
    }

    float acc[2][8][4] = {};

    for (int kt = 0; kt < nkt; ++kt) {
        const int cur = kt & 3;
        asm volatile("cp.async.wait_group 2;\n");
        __syncthreads();   // data ready + all warps done reading slot (kt+3)&3

        if (kt + 3 < nkt) load_stage((kt + 3) & 3, kt + 3);
        asm volatile("cp.async.commit_group;\n");

        #pragma unroll
        for (int kb = 0; kb < 2; kb++) {
            uint4 Aq[2], Bq[4];
            #pragma unroll
            for (int mi = 0; mi < 2; mi++)
                Aq[mi] = sm[cur][kb * 128 + (wm * 2 + mi) * 32 + lane];
            #pragma unroll
            for (int nj = 0; nj < 4; nj++)
                Bq[nj] = sm[cur][256 + kb * 256 + (wn * 4 + nj) * 32 + lane];

            #pragma unroll
            for (int mi = 0; mi < 2; mi++)
                #pragma unroll
                for (int nj = 0; nj < 4; nj++) {
                    mma_f16(acc[mi][nj * 2],     Aq[mi].x, Aq[mi].z, Aq[mi].y, Aq[mi].w,
                            Bq[nj].x, Bq[nj].y);
                    mma_f16(acc[mi][nj * 2 + 1], Aq[mi].x, Aq[mi].z, Aq[mi].y, Aq[mi].w,
                            Bq[nj].z, Bq[nj].w);
                }
        }
    }

    // Epilogue
    if (EPI == 3) {
        // fused QKV: route by output column group (uniform per CTA)
        const int w  = n0 >> 10;            // 0=Q, 1=K, 2=V
        const int nb = n0 & 1023;           // column base within the target
        #pragma unroll
        for (int mi = 0; mi < 2; mi++) {
            #pragma unroll
            for (int nt = 0; nt < 8; nt++) {
                const int r0 = m0 + wm * 32 + mi * 16 + (lane >> 2);
                const int c0 = nb + wn * 64 + nt * 8 + 2 * (lane & 3);
                if (w == 0) {
                    const long off = blk_off(r0, c0, Dm);
                    *(uint32_t*)(g_Qh + off)     = pack2(acc[mi][nt][0], acc[mi][nt][1]);
                    *(uint32_t*)(g_Qh + off + 4) = pack2(acc[mi][nt][2], acc[mi][nt][3]);
                } else if (w == 1) {
                    const long off = blk_off(r0, c0, Dm);
                    *(uint32_t*)(g_Kh + off)     = pack2(acc[mi][nt][0], acc[mi][nt][1]);
                    *(uint32_t*)(g_Kh + off + 4) = pack2(acc[mi][nt][2], acc[mi][nt][3]);
                } else {
                    const int b   = r0 >> 11;
                    const int rb0 = r0 & 2047;
                    __half* Vb = g_Vt + (long)b * Sq * Dm;
                    Vb[blk_off(c0,     rb0,     Sq)] = __float2half_rn(acc[mi][nt][0]);
                    Vb[blk_off(c0 + 1, rb0,     Sq)] = __float2half_rn(acc[mi][nt][1]);
                    Vb[blk_off(c0,     rb0 + 8, Sq)] = __float2half_rn(acc[mi][nt][2]);
                    Vb[blk_off(c0 + 1, rb0 + 8, Sq)] = __float2half_rn(acc[mi][nt][3]);
                }
            }
        }
    } else if (EPI == 4) {
        __half* Cf = (__half*)Cout + (long)blockIdx.z * sC;
        #pragma unroll
        for (int mi = 0; mi < 2; mi++) {
            #pragma unroll
            for (int nt = 0; nt < 8; nt++) {
                const int r0 = m0 + wm * 32 + mi * 16 + (lane >> 2);
                const int c0 = n0 + wn * 64 + nt * 8 + 2 * (lane & 3);
                *(uint32_t*)&Cf[(long)r0 * ldc + c0] =
                    pack2(acc[mi][nt][0], acc[mi][nt][1]);
                *(uint32_t*)&Cf[(long)(r0 + 8) * ldc + c0] =
                    pack2(acc[mi][nt][2], acc[mi][nt][3]);
            }
        }
    } else {
        float* Cf = (float*)Cout + (long)blockIdx.z * sC;
        #pragma unroll
        for (int mi = 0; mi < 2; mi++) {
            #pragma unroll
            for (int nt = 0; nt < 8; nt++) {
                const int r0 = m0 + wm * 32 + mi * 16 + (lane >> 2);
                const int c0 = n0 + wn * 64 + nt * 8 + 2 * (lane & 3);
                *(float2*)&Cf[(long)r0 * ldc + c0] =
                    make_float2(acc[mi][nt][0], acc[mi][nt][1]);
                *(float2*)&Cf[(long)(r0 + 8) * ldc + c0] =
                    make_float2(acc[mi][nt][2], acc[mi][nt][3]);
            }
        }
    }
}

// ---------------------------------------------------------------------------
// Causal row softmax: fp16 scores (row-major) -> fp16 probs (blocked).
// Logits s/32.  Zero-fills [len, ceil64(len)); PV reads exactly that far.
// Each thread loads one 16B oct (8 halves); 2048/8 = 256 = blockDim.
// ---------------------------------------------------------------------------
__global__ void __launch_bounds__(256)
softmax_k(const __half* __restrict__ S, __half* __restrict__ Ph)
{
    const int row = blockIdx.x;
    const int b = row >> 11;
    const int i = row & 2047;
    const __half* p = S + ((long)b * Sq + i) * Sq;
    __half* ph = Ph + (long)b * Sq * Sq;
    const int tid = threadIdx.x;
    const int len = i + 1;
    const int lenPad = (len + 63) & ~63;
    const int noct = lenPad >> 3;

    float e[8];
    const int j0 = tid * 8;
    if (tid < noct) {
        uint4 u = ((const uint4*)p)[tid];
        const __half* h = (const __half*)&u;
        #pragma unroll
        for (int s = 0; s < 8; s++)
            e[s] = (j0 + s < len) ? __half2float(h[s]) : -3.4e38f;
    } else {
        #pragma unroll
        for (int s = 0; s < 8; s++) e[s] = -3.4e38f;
    }

    float mx = -3.4e38f;
    #pragma unroll
    for (int s = 0; s < 8; s++) mx = fmaxf(mx, e[s]);
    mx = warp_max(mx);

    __shared__ float red[8];
    if ((tid & 31) == 0) red[tid >> 5] = mx;
    __syncthreads();
    mx = red[0];
    #pragma unroll
    for (int w = 1; w < 8; w++) mx = fmaxf(mx, red[w]);

    float sum = 0.f;
    #pragma unroll
    for (int s = 0; s < 8; s++) {
        e[s] = __expf((e[s] - mx) * 0.03125f);
        sum += e[s];
    }
    sum = warp_sum(sum);
    __syncthreads();
    if ((tid & 31) == 0) red[tid >> 5] = sum;
    __syncthreads();
    float tot = 0.f;
    #pragma unroll
    for (int w = 0; w < 8; w++) tot += red[w];
    const float inv = 1.0f / tot;

    if (tid < noct) {
        #pragma unroll
        for (int s = 0; s < 8; s += 2)
            *(uint32_t*)(ph + blk_off(i, j0 + s, Sq)) =
                pack2(e[s] * inv, e[s + 1] * inv);
    }
}

// ---------------------------------------------------------------------------
extern "C" void kernel_launch(void* const* d_in, const int* in_sizes, int n_in,
                              void* d_out, int out_size)
{
    const float* x  = (const float*)d_in[0];
    const float* Wq = (const float*)d_in[1];
    const float* Wk = (const float*)d_in[2];
    const float* Wv = (const float*)d_in[3];
    float* out = (float*)d_out;

    __half *Xh, *Wcat, *Qh, *Kh, *Vt, *Sh, *Ph;
    cudaGetSymbolAddress((void**)&Xh,   g_Xh);
    cudaGetSymbolAddress((void**)&Wcat, g_Wcat);
    cudaGetSymbolAddress((void**)&Qh,   g_Qh);
    cudaGetSymbolAddress((void**)&Kh,   g_Kh);
    cudaGetSymbolAddress((void**)&Vt,   g_Vt);
    cudaGetSymbolAddress((void**)&Sh,   g_Sh);
    cudaGetSymbolAddress((void**)&Ph,   g_Ph);

    // Max shared-memory carveout so 4 CTAs x 48KB fit per SM
    cudaFuncSetAttribute((const void*)hgemm<false, false, false, 3>,
        cudaFuncAttributePreferredSharedMemoryCarveout, 100);
    cudaFuncSetAttribute((const void*)hgemm<true, false, true, 4>,
        cudaFuncAttributePreferredSharedMemoryCarveout, 100);
    cudaFuncSetAttribute((const void*)hgemm<false, true, true, 0>,
        cudaFuncAttributePreferredSharedMemoryCarveout, 100);

    const int M = Bsz * Sq;   // 8192

    // 0) pack x; pack all three W^T in ONE launch
    {
        const long nth = (long)M * Dm / 16;
        pack_rm<<<(int)((nth + 255) / 256), 256>>>(x, Xh, Dm, nth);
        dim3 tb(32, 8);
        dim3 gw(Dm / 32, Dm / 32, 3);
        pack_t3<<<gw, tb>>>(Wq, Wk, Wv, Wcat);
    }

    // 1) Fused QKV projection: one launch, epilogue routes Q/K/Vt
    {
        dim3 grid((3 * Dm) / 128, M / 64, 1);
        hgemm<false, false, false, 3><<<grid, 128>>>(
            Xh, Wcat, nullptr, Dm, Dm, 0, 0, 0);
    }

    // 2) Scores: S_b = Q_b K_b^T (causal-skip, heavy rows first), fp16 out
    {
        dim3 grid(Sq / 128, Sq / 64, Bsz);
        hgemm<true, false, true, 4><<<grid, 128>>>(
            Qh, Kh, Sh, Dm, Sq,
            (long)Sq * Dm, (long)Sq * Dm, (long)Sq * Sq);
    }

    // 3) Softmax -> fp16 blocked probs
    softmax_k<<<Bsz * Sq, 256>>>(Sh, Ph);

    // 4) O = P Vt^T (causal K-limit, heavy rows first), fp32 out
    {
        dim3 grid(Dm / 128, Sq / 64, Bsz);
        hgemm<false, true, true, 0><<<grid, 128>>>(
            Ph, Vt, out, Sq, Dm,
            (long)Sq * Sq, (long)Sq * Dm, (long)Sq * Dm);
    }

    (void)in_sizes; (void)n_in; (void)out_size;
}

// round 15
// speedup vs baseline: 1.4681x; 1.0386x over previous
#include <cuda_runtime.h>
#include <cuda_fp16.h>
#include <cstdint>

// Problem constants
constexpr int Bsz = 4;
constexpr int Sq  = 2048;
constexpr int Dm  = 1024;

// Scratch (device globals; no allocation allowed).
// "blocked" fp16 layout: matrix [R x K] split into 16x16 blocks, block
// (br,bk) stored at (br*(K/16)+bk)*256 halves; inside a block, 16B chunk
// (g,q), g=0..7,q=0..3 (chunk idx = g*4+q), holds halves
//   x: [row g,   k 2q,2q+1]   y: [row g,   k 2q+8,2q+9]
//   z: [row g+8, k 2q,2q+1]   w: [row g+8, k 2q+8,2q+9]
// One LDS.128 = one full m16n8k16 A-fragment (regs x,z,y,w) or two
// B-fragments (n=g via x,y and n=g+8 via z,w).
__device__ __half g_Xh  [(long)Bsz * Sq * Dm];
__device__ __half g_Wcat[(long)3 * Dm * Dm];    // WqT | WkT | WvT (row-concat)
__device__ __half g_Qh  [(long)Bsz * Sq * Dm];
__device__ __half g_Kh  [(long)Bsz * Sq * Dm];
__device__ __half g_Vt  [(long)Bsz * Sq * Dm];  // V^T per batch, blocked
__device__ __half g_Ph  [(long)Bsz * Sq * Sq];  // E = exp(s/32) masked, blocked
__device__ float  g_Psum[(long)Bsz * Sq * 16];  // per-row partial sums (16 n-slots)
__device__ float  g_Inv [(long)Bsz * Sq];       // 1 / row sum

// ---------------------------------------------------------------------------
// helpers
// ---------------------------------------------------------------------------
__device__ __forceinline__ void cp16(void* s, const void* g) {
    uint32_t sa = (uint32_t)__cvta_generic_to_shared(s);
    asm volatile("cp.async.cg.shared.global [%0], [%1], 16;\n" :: "r"(sa), "l"(g));
}

__device__ __forceinline__ void mma_f16(float* d,
    uint32_t a0, uint32_t a1, uint32_t a2, uint32_t a3,
    uint32_t b0, uint32_t b1) {
    asm volatile(
        "mma.sync.aligned.m16n8k16.row.col.f32.f16.f16.f32 "
        "{%0,%1,%2,%3},{%4,%5,%6,%7},{%8,%9},{%0,%1,%2,%3};"
        : "+f"(d[0]), "+f"(d[1]), "+f"(d[2]), "+f"(d[3])
        : "r"(a0), "r"(a1), "r"(a2), "r"(a3), "r"(b0), "r"(b1));
}

__device__ __forceinline__ uint32_t pack2(float a, float b) {
    __half2 h = __floats2half2_rn(a, b);
    return *(uint32_t*)&h;
}

// half offset of element (r, k) inside blocked [R x K] matrix (Kd = K size).
__device__ __forceinline__ long blk_off(int r, int k, int Kd) {
    return ((long)(r >> 4) * (Kd >> 4) + (k >> 4)) * 256
         + ((r & 7) * 4 + ((k >> 1) & 3)) * 8
         + ((r >> 3) & 1) * 4 + ((k >> 3) & 1) * 2 + (k & 1);
}

// ---------------------------------------------------------------------------
// Pack fp32 row-major [R x Kd] -> fp16 blocked.  One thread produces TWO
// adjacent 16B chunks from 4 coalesced float4 loads.  nth = R*Kd/16.
// ---------------------------------------------------------------------------
__global__ void __launch_bounds__(256)
pack_rm(const float* __restrict__ in, __half* __restrict__ out,
        int Kd, long nth)
{
    long t = (long)blockIdx.x * blockDim.x + threadIdx.x;
    if (t >= nth) return;
    const long blk = t >> 4;
    const int sub = (int)(t & 15);
    const int g = sub >> 1, qh = sub & 1;
    const int Kb = Kd >> 4;
    const int rb = (int)(blk / Kb), kb = (int)(blk % Kb);
    const int r = rb * 16 + g;
    const float* p = in + (long)r * Kd + kb * 16 + qh * 4;
    float4 lo  = *(const float4*)p;
    float4 lo8 = *(const float4*)(p + 8);
    float4 hi  = *(const float4*)(p + (long)8 * Kd);
    float4 hi8 = *(const float4*)(p + (long)8 * Kd + 8);
    uint4 u0, u1;
    u0.x = pack2(lo.x, lo.y);   u0.y = pack2(lo8.x, lo8.y);
    u0.z = pack2(hi.x, hi.y);   u0.w = pack2(hi8.x, hi8.y);
    u1.x = pack2(lo.z, lo.w);   u1.y = pack2(lo8.z, lo8.w);
    u1.z = pack2(hi.z, hi.w);   u1.w = pack2(hi8.z, hi8.w);
    uint4* o = (uint4*)out + blk * 32 + g * 4 + 2 * qh;
    o[0] = u0;
    o[1] = u1;
}

// ---------------------------------------------------------------------------
// Transpose 3 fp32 [Dm x Dm] weights -> fp16 blocked [Dm x Dm] each, into
// one concatenated buffer.  blockIdx.z selects the source.
// ---------------------------------------------------------------------------
__global__ void __launch_bounds__(256)
pack_t3(const float* __restrict__ w0, const float* __restrict__ w1,
        const float* __restrict__ w2, __half* __restrict__ out)
{
    __shared__ float t[32][33];
    const float* in = (blockIdx.z == 0) ? w0 : (blockIdx.z == 1) ? w1 : w2;
    __half* o = out + (long)blockIdx.z * Dm * Dm;
    const int r0 = blockIdx.x * 32, c0 = blockIdx.y * 32;
    const int x = threadIdx.x, y = threadIdx.y;     // (32, 8)
    #pragma unroll
    for (int i = 0; i < 32; i += 8)
        t[y + i][x] = in[(long)(r0 + y + i) * Dm + c0 + x];
    __syncthreads();

    const int tid = y * 32 + x;
    if (tid < 128) {
        const int blk = tid >> 5, idx = tid & 31;
        const int brl = blk >> 1, bkl = blk & 1;
        const int g = idx >> 2, q = idx & 3;
        const int E  = 16 * brl + g;       // out-row within 32 (orig col)
        const int S0 = 16 * bkl + 2 * q;   // out-k within 32 (orig row)
        uint4 u;
        u.x = pack2(t[S0][E],         t[S0 + 1][E]);
        u.y = pack2(t[S0 + 8][E],     t[S0 + 9][E]);
        u.z = pack2(t[S0][E + 8],     t[S0 + 1][E + 8]);
        u.w = pack2(t[S0 + 8][E + 8], t[S0 + 9][E + 8]);
        const long chunk =
            ((long)((c0 >> 4) + brl) * (Dm >> 4) + (r0 >> 4) + bkl) * 32 + idx;
        ((uint4*)o)[chunk] = u;
    }
}

// ---------------------------------------------------------------------------
// Row-sum finisher: Inv[row] = 1 / sum of that row's partial sums.
// Row i (batch-local) has partials in slots 0..((i&~63)+63)>>7.
// ---------------------------------------------------------------------------
__global__ void __launch_bounds__(256)
rowsum_k()
{
    const int row = blockIdx.x * 256 + threadIdx.x;    // 0 .. Bsz*Sq-1
    const int i = row & (Sq - 1);
    const int nbmax = ((i & ~63) + 63) >> 7;
    const float* p = g_Psum + (long)row * 16;
    float s = 0.f;
    for (int nb = 0; nb <= nbmax; nb++) s += p[nb];
    g_Inv[row] = 1.0f / s;
}

// ---------------------------------------------------------------------------
// FP16 mma.sync GEMM on blocked operands:  C[M,N] = A[M,K] * B[N,K]^T
// CTA 64(M) x 128(N), 4 warps (2x2), warp tile 32x64.
// K-chunk 32 per stage, 4 stages, ONE __syncthreads per chunk.
// __launch_bounds__(128, 4).
// REVY: reverse blockIdx.y -> m0 so heaviest CTAs launch first.
// EPI: 3 = fused QKV routing (Q/K blocked, V transposed blocked per batch)
//      5 = scores: mask + exp(s/32) -> blocked fp16 E into g_Ph (batched),
//          plus per-row partial sums into g_Psum
//      6 = PV: fp32 row-major scaled by g_Inv[row]
// ---------------------------------------------------------------------------
template <bool CAUSAL_SKIP, bool KLIMIT, bool REVY, int EPI>
__global__ void __launch_bounds__(128, 4)
hgemm(const __half* __restrict__ A, const __half* __restrict__ B, void* Cout,
      int Kd, int ldc, long sA, long sB, long sC)
{
    const int by = REVY ? (gridDim.y - 1 - blockIdx.y) : blockIdx.y;
    const int m0 = by * 64;
    const int n0 = blockIdx.x * 128;
    if (CAUSAL_SKIP && n0 > m0 + 63) return;

    A += (long)blockIdx.z * sA;
    B += (long)blockIdx.z * sB;

    const int Keff = KLIMIT ? min(Kd, m0 + 64) : Kd;
    const int nkt  = Keff >> 5;          // K-chunks of 32
    const int Kb   = Kd >> 4;            // 16-K blocks per row

    // per stage: A [0,256) = kb*128 + mb*32 + lane ; B [256,768)
    __shared__ uint4 sm[4][768];         // 48 KB

    const int tid  = threadIdx.x;
    const int warp = tid >> 5;           // 0..3
    const int lane = tid & 31;
    const int wm   = warp >> 1;          // 0..1 (32 M-rows)
    const int wn   = warp & 1;           // 0..1 (64 N-cols)

    // A loader: 256 chunks per stage, 2/thread
    const uint4* agp[2];  int asmi[2];
    #pragma unroll
    for (int i = 0; i < 2; i++) {
        const int c  = tid + i * 128;
        const int kb = c >> 7, mb = (c >> 5) & 3, ln = c & 31;
        agp[i]  = (const uint4*)A + ((long)((m0 >> 4) + mb) * Kb + kb) * 32 + ln;
        asmi[i] = kb * 128 + mb * 32 + ln;
    }
    // B loader: 512 chunks per stage, 4/thread
    const uint4* bgp[4];  int bsmi[4];
    #pragma unroll
    for (int i = 0; i < 4; i++) {
        const int c  = tid + i * 128;
        const int kb = c >> 8, nb = (c >> 5) & 7, ln = c & 31;
        bgp[i]  = (const uint4*)B + ((long)((n0 >> 4) + nb) * Kb + kb) * 32 + ln;
        bsmi[i] = 256 + kb * 256 + nb * 32 + ln;
    }

    auto load_stage = [&](int st, int kt) {
        const long koff = (long)kt * 64;   // 2 blocks of 32 chunks per K32
        #pragma unroll
        for (int i = 0; i < 2; i++) cp16(&sm[st][asmi[i]], agp[i] + koff);
        #pragma unroll
        for (int i = 0; i < 4; i++) cp16(&sm[st][bsmi[i]], bgp[i] + koff);
    };

    #pragma unroll
    for (int s = 0; s < 3; s++) {
        if (s < nkt) load_stage(s, s);
        asm volatile("cp.async.commit_group;\n");
    }

    float acc[2][8][4] = {};

    for (int kt = 0; kt < nkt; ++kt) {
        const int cur = kt & 3;
        asm volatile("cp.async.wait_group 2;\n");
        __syncthreads();   // data ready + all warps done reading slot (kt+3)&3

        if (kt + 3 < nkt) load_stage((kt + 3) & 3, kt + 3);
        asm volatile("cp.async.commit_group;\n");

        #pragma unroll
        for (int kb = 0; kb < 2; kb++) {
            uint4 Aq[2], Bq[4];
            #pragma unroll
            for (int mi = 0; mi < 2; mi++)
                Aq[mi] = sm[cur][kb * 128 + (wm * 2 + mi) * 32 + lane];
            #pragma unroll
            for (int nj = 0; nj < 4; nj++)
                Bq[nj] = sm[cur][256 + kb * 256 + (wn * 4 + nj) * 32 + lane];

            #pragma unroll
            for (int mi = 0; mi < 2; mi++)
                #pragma unroll
                for (int nj = 0; nj < 4; nj++) {
                    mma_f16(acc[mi][nj * 2],     Aq[mi].x, Aq[mi].z, Aq[mi].y, Aq[mi].w,
                            Bq[nj].x, Bq[nj].y);
                    mma_f16(acc[mi][nj * 2 + 1], Aq[mi].x, Aq[mi].z, Aq[mi].y, Aq[mi].w,
                            Bq[nj].z, Bq[nj].w);
                }
        }
    }

    // Epilogue
    if (EPI == 3) {
        // fused QKV: route by output column group (uniform per CTA)
        const int w  = n0 >> 10;            // 0=Q, 1=K, 2=V
        const int nb = n0 & 1023;           // column base within the target
        #pragma unroll
        for (int mi = 0; mi < 2; mi++) {
            #pragma unroll
            for (int nt = 0; nt < 8; nt++) {
                const int r0 = m0 + wm * 32 + mi * 16 + (lane >> 2);
                const int c0 = nb + wn * 64 + nt * 8 + 2 * (lane & 3);
                if (w == 0) {
                    const long off = blk_off(r0, c0, Dm);
                    *(uint32_t*)(g_Qh + off)     = pack2(acc[mi][nt][0], acc[mi][nt][1]);
                    *(uint32_t*)(g_Qh + off + 4) = pack2(acc[mi][nt][2], acc[mi][nt][3]);
                } else if (w == 1) {
                    const long off = blk_off(r0, c0, Dm);
                    *(uint32_t*)(g_Kh + off)     = pack2(acc[mi][nt][0], acc[mi][nt][1]);
                    *(uint32_t*)(g_Kh + off + 4) = pack2(acc[mi][nt][2], acc[mi][nt][3]);
                } else {
                    const int b   = r0 >> 11;
                    const int rb0 = r0 & 2047;
                    __half* Vb = g_Vt + (long)b * Sq * Dm;
                    Vb[blk_off(c0,     rb0,     Sq)] = __float2half_rn(acc[mi][nt][0]);
                    Vb[blk_off(c0 + 1, rb0,     Sq)] = __float2half_rn(acc[mi][nt][1]);
                    Vb[blk_off(c0,     rb0 + 8, Sq)] = __float2half_rn(acc[mi][nt][2]);
                    Vb[blk_off(c0 + 1, rb0 + 8, Sq)] = __float2half_rn(acc[mi][nt][3]);
                }
            }
        }
    } else if (EPI == 5) {
        // scores: causal mask, E = exp(s/32) (fp32), blocked store, row sums
        __half* Eb = g_Ph + (long)blockIdx.z * Sq * Sq;
        const int lg = lane >> 2, q = lane & 3;
        float rs[2][2] = {{0.f, 0.f}, {0.f, 0.f}};
        #pragma unroll
        for (int mi = 0; mi < 2; mi++) {
            const int ra = m0 + wm * 32 + mi * 16 + lg;
            #pragma unroll
            for (int nt = 0; nt < 8; nt++) {
                const int c0 = n0 + wn * 64 + nt * 8 + 2 * q;
                const float e00 = (c0     <= ra    ) ? __expf(acc[mi][nt][0] * 0.03125f) : 0.f;
                const float e01 = (c0 + 1 <= ra    ) ? __expf(acc[mi][nt][1] * 0.03125f) : 0.f;
                const float e10 = (c0     <= ra + 8) ? __expf(acc[mi][nt][2] * 0.03125f) : 0.f;
                const float e11 = (c0 + 1 <= ra + 8) ? __expf(acc[mi][nt][3] * 0.03125f) : 0.f;
                *(uint32_t*)(Eb + blk_off(ra,     c0, Sq)) = pack2(e00, e01);
                *(uint32_t*)(Eb + blk_off(ra + 8, c0, Sq)) = pack2(e10, e11);
                rs[mi][0] += e00 + e01;
                rs[mi][1] += e10 + e11;
            }
        }
        #pragma unroll
        for (int mi = 0; mi < 2; mi++)
            #pragma unroll
            for (int hi = 0; hi < 2; hi++) {
                rs[mi][hi] += __shfl_xor_sync(0xFFFFFFFFu, rs[mi][hi], 1);
                rs[mi][hi] += __shfl_xor_sync(0xFFFFFFFFu, rs[mi][hi], 2);
            }
        __syncthreads();                     // mainloop smem reads all done
        float* ps = (float*)&sm[0][0];       // reuse stage-0 smem (64x2 floats)
        if (q == 0) {
            #pragma unroll
            for (int mi = 0; mi < 2; mi++)
                #pragma unroll
                for (int hi = 0; hi < 2; hi++)
                    ps[(wm * 32 + mi * 16 + hi * 8 + lg) * 2 + wn] = rs[mi][hi];
        }
        __syncthreads();
        if (tid < 64)
            g_Psum[((long)blockIdx.z * Sq + m0 + tid) * 16 + (n0 >> 7)] =
                ps[tid * 2] + ps[tid * 2 + 1];
    } else {
        // EPI == 6: PV output, scaled by per-row inverse sum
        float* Cf = (float*)Cout + (long)blockIdx.z * sC;
        const float* Iv = g_Inv + (long)blockIdx.z * Sq;
        #pragma unroll
        for (int mi = 0; mi < 2; mi++) {
            const int r0 = m0 + wm * 32 + mi * 16 + (lane >> 2);
            const float i0 = Iv[r0], i1 = Iv[r0 + 8];
            #pragma unroll
            for (int nt = 0; nt < 8; nt++) {
                const int c0 = n0 + wn * 64 + nt * 8 + 2 * (lane & 3);
                *(float2*)&Cf[(long)r0 * ldc + c0] =
                    make_float2(acc[mi][nt][0] * i0, acc[mi][nt][1] * i0);
                *(float2*)&Cf[(long)(r0 + 8) * ldc + c0] =
                    make_float2(acc[mi][nt][2] * i1, acc[mi][nt][3] * i1);
            }
        }
    }
}

// ---------------------------------------------------------------------------
extern "C" void kernel_launch(void* const* d_in, const int* in_sizes, int n_in,
                              void* d_out, int out_size)
{
    const float* x  = (const float*)d_in[0];
    const float* Wq = (const float*)d_in[1];
    const float* Wk = (const float*)d_in[2];
    const float* Wv = (const float*)d_in[3];
    float* out = (float*)d_out;

    __half *Xh, *Wcat, *Qh, *Kh, *Vt, *Ph;
    cudaGetSymbolAddress((void**)&Xh,   g_Xh);
    cudaGetSymbolAddress((void**)&Wcat, g_Wcat);
    cudaGetSymbolAddress((void**)&Qh,   g_Qh);
    cudaGetSymbolAddress((void**)&Kh,   g_Kh);
    cudaGetSymbolAddress((void**)&Vt,   g_Vt);
    cudaGetSymbolAddress((void**)&Ph,   g_Ph);

    // Max shared-memory carveout so 4 CTAs x 48KB fit per SM
    cudaFuncSetAttribute((const void*)hgemm<false, false, false, 3>,
        cudaFuncAttributePreferredSharedMemoryCarveout, 100);
    cudaFuncSetAttribute((const void*)hgemm<true, false, true, 5>,
        cudaFuncAttributePreferredSharedMemoryCarveout, 100);
    cudaFuncSetAttribute((const void*)hgemm<false, true, true, 6>,
        cudaFuncAttributePreferredSharedMemoryCarveout, 100);

    const int M = Bsz * Sq;   // 8192

    // 0) pack x; pack all three W^T in ONE launch
    {
        const long nth = (long)M * Dm / 16;
        pack_rm<<<(int)((nth + 255) / 256), 256>>>(x, Xh, Dm, nth);
        dim3 tb(32, 8);
        dim3 gw(Dm / 32, Dm / 32, 3);
        pack_t3<<<gw, tb>>>(Wq, Wk, Wv, Wcat);
    }

    // 1) Fused QKV projection: one launch, epilogue routes Q/K/Vt
    {
        dim3 grid((3 * Dm) / 128, M / 64, 1);
        hgemm<false, false, false, 3><<<grid, 128>>>(
            Xh, Wcat, nullptr, Dm, Dm, 0, 0, 0);
    }

    // 2) Scores + mask + exp + partial row sums (causal-skip, heavy first)
    {
        dim3 grid(Sq / 128, Sq / 64, Bsz);
        hgemm<true, false, true, 5><<<grid, 128>>>(
            Qh, Kh, nullptr, Dm, Sq,
            (long)Sq * Dm, (long)Sq * Dm, 0);
    }

    // 3) Row-sum finisher -> Inv
    rowsum_k<<<(Bsz * Sq) / 256, 256>>>();

    // 4) O = (E Vt^T) * Inv (causal K-limit, heavy rows first), fp32 out
    {
        dim3 grid(Dm / 128, Sq / 64, Bsz);
        hgemm<false, true, true, 6><<<grid, 128>>>(
            Ph, Vt, out, Sq, Dm,
            (long)Sq * Sq, (long)Sq * Dm, (long)Sq * Dm);
    }

    (void)in_sizes; (void)n_in; (void)out_size;
}